// round 6
// baseline (speedup 1.0000x reference)
#include <cuda_runtime.h>
#include <math.h>
#include <stdint.h>

#define NTOK 2048
#define DDIM 1024
#define NEXP 14
#define FDIM 2048
#define NPAIR (2*NTOK)
#define MPAD  (NPAIR + 128)

typedef unsigned long long ull;

// ---------------- device scratch ---------------------------------------------
__device__ int   g_count[NEXP];
__device__ int   g_offset[NEXP];
__device__ int   g_pairs[NEXP][NTOK];      // value = token*2 + slot
__device__ float g_gatew[NTOK][2];
__device__ float g_h1[MPAD][FDIM];         // gemm1 output, row = offset[e]+m
__device__ float g_out2[NPAIR][DDIM];      // gemm2 output, row = pair id

// ---------------- packed f32x2 helpers ----------------------------------------
__device__ __forceinline__ ull bcast2(float v) {
    ull r;
    asm("mov.b64 %0, {%1,%1};" : "=l"(r) : "r"(__float_as_uint(v)));
    return r;
}
__device__ __forceinline__ void fma2(ull& d, ull a, ull b) {
    asm("fma.rn.f32x2 %0, %1, %2, %0;" : "+l"(d) : "l"(a), "l"(b));
}
__device__ __forceinline__ void unpack2(ull v, float& lo, float& hi) {
    uint32_t a, b;
    asm("mov.b64 {%0,%1}, %2;" : "=r"(a), "=r"(b) : "l"(v));
    lo = __uint_as_float(a);
    hi = __uint_as_float(b);
}

// ---------------- kernel: zero expert counts ----------------------------------
__global__ void zero_kernel() {
    if (threadIdx.x < NEXP) g_count[threadIdx.x] = 0;
}

// ---------------- kernel: gating (R1-proven) -----------------------------------
__global__ void gate_kernel(const float* __restrict__ x,
                            const float* __restrict__ gw) {
    int n = blockIdx.x;
    __shared__ float sx[DDIM];
    __shared__ float red[128];
    __shared__ float logits[NEXP];
    const float* xr = x + (size_t)n * DDIM;
    for (int d = threadIdx.x; d < DDIM; d += 128) sx[d] = xr[d];
    __syncthreads();
    for (int e = 0; e < NEXP; e++) {
        const float* w = gw + (size_t)e * DDIM;
        float s = 0.f;
        for (int d = threadIdx.x; d < DDIM; d += 128) s += sx[d] * w[d];
        red[threadIdx.x] = s;
        __syncthreads();
        #pragma unroll
        for (int st = 64; st > 0; st >>= 1) {
            if (threadIdx.x < st) red[threadIdx.x] += red[threadIdx.x + st];
            __syncthreads();
        }
        if (threadIdx.x == 0) logits[e] = red[0];
        __syncthreads();
    }
    if (threadIdx.x == 0) {
        int i0 = 0; float l0 = logits[0];
        for (int e = 1; e < NEXP; e++) if (logits[e] > l0) { l0 = logits[e]; i0 = e; }
        int i1 = -1; float l1 = -3.0e38f;
        for (int e = 0; e < NEXP; e++) if (e != i0 && logits[e] > l1) { l1 = logits[e]; i1 = e; }
        float p1 = expf(l1 - l0);
        float inv = 1.0f / (1.0f + p1);
        g_gatew[n][0] = inv;
        g_gatew[n][1] = p1 * inv;
        int s0 = atomicAdd(&g_count[i0], 1);
        g_pairs[i0][s0] = n * 2 + 0;
        int s1 = atomicAdd(&g_count[i1], 1);
        g_pairs[i1][s1] = n * 2 + 1;
    }
}

__global__ void prefix_kernel() {
    if (threadIdx.x == 0) {
        int s = 0;
        for (int e = 0; e < NEXP; e++) { g_offset[e] = s; s += g_count[e]; }
    }
}

// ---------------- shared chunk compute: 16 k-steps, 8x8/thread, f32x2 ---------
__device__ __forceinline__ void compute_chunk(
    const float (*As)[128], const float (*Bs)[128],
    ull (&acc)[4][8], int m0, int n0)
{
    #pragma unroll
    for (int kk = 0; kk < 16; kk++) {
        ulonglong2 a01 = *(const ulonglong2*)&As[kk][m0];
        ulonglong2 a23 = *(const ulonglong2*)&As[kk][m0 + 4];
        ull a2[4] = { a01.x, a01.y, a23.x, a23.y };
        float4 bA = *(const float4*)&Bs[kk][n0];
        float4 bB = *(const float4*)&Bs[kk][n0 + 4];
        ull bb[8] = { bcast2(bA.x), bcast2(bA.y), bcast2(bA.z), bcast2(bA.w),
                      bcast2(bB.x), bcast2(bB.y), bcast2(bB.z), bcast2(bB.w) };
        #pragma unroll
        for (int i = 0; i < 4; i++)
            #pragma unroll
            for (int j = 0; j < 8; j++)
                fma2(acc[i][j], a2[i], bb[j]);
    }
}

// ---------------- GEMM1: h1 = gelu(gather(x) @ w1[e] + b1[e]) ------------------
// CTA tile 128x128, k-chunk 16, 256 threads (16x16), thread tile 8x8.
__global__ void __launch_bounds__(256)
gemm1_kernel(const float* __restrict__ x,
             const float* __restrict__ w1,
             const float* __restrict__ b1) {
    int e = blockIdx.z, mt = blockIdx.y;
    int cnt = g_count[e];
    if (mt * 128 >= cnt) return;
    int nt = blockIdx.x;
    int off = g_offset[e];

    __shared__ float As[16][128];
    __shared__ float Bs[16][128];
    __shared__ int rowtok[128];

    int tid = threadIdx.x;
    int tx = tid & 15, ty = tid >> 4;
    int m0 = ty * 8, n0 = tx * 8;

    if (tid < 128) {
        int m = mt * 128 + tid;
        rowtok[tid] = (m < cnt) ? (g_pairs[e][m] >> 1) : -1;
    }
    __syncthreads();

    // copy-thread mapping
    int am = tid >> 1, aks = (tid & 1) * 8;           // A: 2 thr/row, 8 k each
    int bk = tid >> 4, bi = tid & 15;                 // B: 16 thr/row
    int t = rowtok[am];
    const float* w1e = w1 + (size_t)e * DDIM * FDIM + nt * 128;

    ull acc[4][8] = {};
    float4 av0, av1, bu0, bu1;

    auto load_regs = [&](int k0) {
        av0 = make_float4(0.f, 0.f, 0.f, 0.f); av1 = av0;
        if (t >= 0) {
            const float4* src = (const float4*)(x + (size_t)t * DDIM + k0 + aks);
            av0 = src[0]; av1 = src[1];
        }
        const float4* wrow = (const float4*)(w1e + (size_t)(k0 + bk) * FDIM);
        bu0 = wrow[bi];
        bu1 = wrow[bi + 16];
    };
    auto store_smem = [&]() {
        As[aks + 0][am] = av0.x; As[aks + 1][am] = av0.y;
        As[aks + 2][am] = av0.z; As[aks + 3][am] = av0.w;
        As[aks + 4][am] = av1.x; As[aks + 5][am] = av1.y;
        As[aks + 6][am] = av1.z; As[aks + 7][am] = av1.w;
        *(float4*)&Bs[bk][bi * 4]      = bu0;
        *(float4*)&Bs[bk][bi * 4 + 64] = bu1;
    };

    load_regs(0);
    const int NCH = DDIM / 16;
    for (int c = 0; c < NCH; c++) {
        __syncthreads();
        store_smem();
        __syncthreads();
        if (c + 1 < NCH) load_regs((c + 1) * 16);
        compute_chunk(As, Bs, acc, m0, n0);
    }

    // epilogue: bias + exact gelu, store fp32 rows
    int lim = cnt - mt * 128; if (lim > 128) lim = 128;
    const float* b1e = b1 + (size_t)e * FDIM + nt * 128 + n0;
    float bv[8];
    *(float4*)&bv[0] = *(const float4*)&b1e[0];
    *(float4*)&bv[4] = *(const float4*)&b1e[4];
    #pragma unroll
    for (int i = 0; i < 4; i++) {
        float lo[8], hi[8];
        #pragma unroll
        for (int j = 0; j < 8; j++) unpack2(acc[i][j], lo[j], hi[j]);
        #pragma unroll
        for (int h = 0; h < 2; h++) {
            int r = m0 + i * 2 + h;
            if (r < lim) {
                float* dst = &g_h1[off + mt * 128 + r][nt * 128 + n0];
                float o[8];
                #pragma unroll
                for (int j = 0; j < 8; j++) {
                    float v = (h ? hi[j] : lo[j]) + bv[j];
                    o[j] = 0.5f * v * (1.0f + erff(v * 0.70710678118654752440f));
                }
                *(float4*)&dst[0] = *(float4*)&o[0];
                *(float4*)&dst[4] = *(float4*)&o[4];
            }
        }
    }
}

// ---------------- GEMM2: out2 = h1 @ w2[e] + b2[e] -----------------------------
__global__ void __launch_bounds__(256)
gemm2_kernel(const float* __restrict__ w2,
             const float* __restrict__ b2) {
    int e = blockIdx.z, mt = blockIdx.y;
    int cnt = g_count[e];
    if (mt * 128 >= cnt) return;
    int nt = blockIdx.x;
    int off = g_offset[e];

    __shared__ float As[16][128];
    __shared__ float Bs[16][128];
    __shared__ int pid[128];

    int tid = threadIdx.x;
    int tx = tid & 15, ty = tid >> 4;
    int m0 = ty * 8, n0 = tx * 8;

    if (tid < 128) {
        int m = mt * 128 + tid;
        pid[tid] = (m < cnt) ? g_pairs[e][m] : -1;
    }

    int am = tid >> 1, aks = (tid & 1) * 8;
    int bk = tid >> 4, bi = tid & 15;
    const float* arow = g_h1[off + mt * 128 + am];   // in-bounds: < MPAD
    const float* w2e = w2 + (size_t)e * FDIM * DDIM + nt * 128;

    ull acc[4][8] = {};
    float4 av0, av1, bu0, bu1;

    auto load_regs = [&](int k0) {
        const float4* src = (const float4*)(arow + k0 + aks);
        av0 = src[0]; av1 = src[1];
        const float4* wrow = (const float4*)(w2e + (size_t)(k0 + bk) * DDIM);
        bu0 = wrow[bi];
        bu1 = wrow[bi + 16];
    };
    auto store_smem = [&]() {
        As[aks + 0][am] = av0.x; As[aks + 1][am] = av0.y;
        As[aks + 2][am] = av0.z; As[aks + 3][am] = av0.w;
        As[aks + 4][am] = av1.x; As[aks + 5][am] = av1.y;
        As[aks + 6][am] = av1.z; As[aks + 7][am] = av1.w;
        *(float4*)&Bs[bk][bi * 4]      = bu0;
        *(float4*)&Bs[bk][bi * 4 + 64] = bu1;
    };

    load_regs(0);
    const int NCH = FDIM / 16;
    for (int c = 0; c < NCH; c++) {
        __syncthreads();
        store_smem();
        __syncthreads();
        if (c + 1 < NCH) load_regs((c + 1) * 16);
        compute_chunk(As, Bs, acc, m0, n0);
    }

    __syncthreads();   // pid stable (written before first sync, but be safe)
    int lim = cnt - mt * 128; if (lim > 128) lim = 128;
    const float* b2e = b2 + (size_t)e * DDIM + nt * 128 + n0;
    float bv[8];
    *(float4*)&bv[0] = *(const float4*)&b2e[0];
    *(float4*)&bv[4] = *(const float4*)&b2e[4];
    #pragma unroll
    for (int i = 0; i < 4; i++) {
        float lo[8], hi[8];
        #pragma unroll
        for (int j = 0; j < 8; j++) unpack2(acc[i][j], lo[j], hi[j]);
        #pragma unroll
        for (int h = 0; h < 2; h++) {
            int r = m0 + i * 2 + h;
            if (r < lim) {
                int pr = pid[r];
                float* dst = &g_out2[pr][nt * 128 + n0];
                float o[8];
                #pragma unroll
                for (int j = 0; j < 8; j++) o[j] = (h ? hi[j] : lo[j]) + bv[j];
                *(float4*)&dst[0] = *(float4*)&o[0];
                *(float4*)&dst[4] = *(float4*)&o[4];
            }
        }
    }
}

// ---------------- combine: out = clip(x + w0*o0 + w1*o1, +-100) -----------------
__global__ void combine_kernel(const float* __restrict__ x,
                               float* __restrict__ out) {
    int i = blockIdx.x * 256 + threadIdx.x;
    int n = i >> 10;
    int d = i & 1023;
    float v = x[i]
            + g_gatew[n][0] * g_out2[2 * n + 0][d]
            + g_gatew[n][1] * g_out2[2 * n + 1][d];
    out[i] = fminf(fmaxf(v, -100.0f), 100.0f);
}

// ---------------- launch --------------------------------------------------------
extern "C" void kernel_launch(void* const* d_in, const int* in_sizes, int n_in,
                              void* d_out, int out_size) {
    const float* h      = (const float*)d_in[0];   // (2,1024,1024)
    const float* gate_w = (const float*)d_in[1];   // (14,1024)
    const float* w1     = (const float*)d_in[2];   // (14,1024,2048)
    const float* b1     = (const float*)d_in[3];   // (14,2048)
    const float* w2     = (const float*)d_in[4];   // (14,2048,1024)
    const float* b2     = (const float*)d_in[5];   // (14,1024)
    float* out = (float*)d_out;

    zero_kernel<<<1, 32>>>();
    gate_kernel<<<NTOK, 128>>>(h, gate_w);
    prefix_kernel<<<1, 32>>>();
    gemm1_kernel<<<dim3(FDIM / 128, NTOK / 128, NEXP), 256>>>(h, w1, b1);
    gemm2_kernel<<<dim3(DDIM / 128, NTOK / 128, NEXP), 256>>>(w2, b2);
    combine_kernel<<<(NTOK * DDIM) / 256, 256>>>(h, out);
}

// round 7
// speedup vs baseline: 1.2570x; 1.2570x over previous
#include <cuda_runtime.h>
#include <math.h>
#include <stdint.h>
#include <cuda_bf16.h>

#define NTOK 2048
#define DDIM 1024
#define NEXP 14
#define FDIM 2048
#define NPAIR (2*NTOK)
#define MPAD  (NPAIR + 128)

typedef unsigned long long ull;

// ---------------- device scratch ---------------------------------------------
__device__ int   g_count[NEXP];
__device__ int   g_offset[NEXP];
__device__ int   g_pairs[NEXP][NTOK];      // value = token*2 + slot
__device__ float g_gatew[NTOK][2];
__device__ float g_h1[MPAD][FDIM];         // gemm1 output, row = offset[e]+m
__device__ float g_out2[NPAIR][DDIM];      // gemm2 output, row = pair id

// ---------------- packed f32x2 helpers (gemm2, proven R6 path) ----------------
__device__ __forceinline__ ull bcast2(float v) {
    ull r;
    asm("mov.b64 %0, {%1,%1};" : "=l"(r) : "r"(__float_as_uint(v)));
    return r;
}
__device__ __forceinline__ void fma2(ull& d, ull a, ull b) {
    asm("fma.rn.f32x2 %0, %1, %2, %0;" : "+l"(d) : "l"(a), "l"(b));
}
__device__ __forceinline__ void unpack2(ull v, float& lo, float& hi) {
    uint32_t a, b;
    asm("mov.b64 {%0,%1}, %2;" : "=r"(a), "=r"(b) : "l"(v));
    lo = __uint_as_float(a);
    hi = __uint_as_float(b);
}

// ---------------- bf16 helpers (gemm1 mma path) --------------------------------
__device__ __forceinline__ uint32_t pack_bf2(float a, float b) {
    __nv_bfloat162 t = __floats2bfloat162_rn(a, b);
    return *reinterpret_cast<uint32_t*>(&t);
}
__device__ __forceinline__ float bres(float v) {
    return v - __bfloat162float(__float2bfloat16_rn(v));
}

#define MMA_BF16(d, a0, a1, a2, a3, b0, b1) \
    asm volatile("mma.sync.aligned.m16n8k16.row.col.f32.bf16.bf16.f32 " \
        "{%0,%1,%2,%3},{%4,%5,%6,%7},{%8,%9},{%0,%1,%2,%3};" \
        : "+f"((d)[0]), "+f"((d)[1]), "+f"((d)[2]), "+f"((d)[3]) \
        : "r"(a0), "r"(a1), "r"(a2), "r"(a3), "r"(b0), "r"(b1))

// ---------------- kernel: zero expert counts ----------------------------------
__global__ void zero_kernel() {
    if (threadIdx.x < NEXP) g_count[threadIdx.x] = 0;
}

// ---------------- kernel: gating (R1/R6-proven) ---------------------------------
__global__ void gate_kernel(const float* __restrict__ x,
                            const float* __restrict__ gw) {
    int n = blockIdx.x;
    __shared__ float sx[DDIM];
    __shared__ float red[128];
    __shared__ float logits[NEXP];
    const float* xr = x + (size_t)n * DDIM;
    for (int d = threadIdx.x; d < DDIM; d += 128) sx[d] = xr[d];
    __syncthreads();
    for (int e = 0; e < NEXP; e++) {
        const float* w = gw + (size_t)e * DDIM;
        float s = 0.f;
        for (int d = threadIdx.x; d < DDIM; d += 128) s += sx[d] * w[d];
        red[threadIdx.x] = s;
        __syncthreads();
        #pragma unroll
        for (int st = 64; st > 0; st >>= 1) {
            if (threadIdx.x < st) red[threadIdx.x] += red[threadIdx.x + st];
            __syncthreads();
        }
        if (threadIdx.x == 0) logits[e] = red[0];
        __syncthreads();
    }
    if (threadIdx.x == 0) {
        int i0 = 0; float l0 = logits[0];
        for (int e = 1; e < NEXP; e++) if (logits[e] > l0) { l0 = logits[e]; i0 = e; }
        int i1 = -1; float l1 = -3.0e38f;
        for (int e = 0; e < NEXP; e++) if (e != i0 && logits[e] > l1) { l1 = logits[e]; i1 = e; }
        float p1 = expf(l1 - l0);
        float inv = 1.0f / (1.0f + p1);
        g_gatew[n][0] = inv;
        g_gatew[n][1] = p1 * inv;
        int s0 = atomicAdd(&g_count[i0], 1);
        g_pairs[i0][s0] = n * 2 + 0;
        int s1 = atomicAdd(&g_count[i1], 1);
        g_pairs[i1][s1] = n * 2 + 1;
    }
}

__global__ void prefix_kernel() {
    if (threadIdx.x == 0) {
        int s = 0;
        for (int e = 0; e < NEXP; e++) { g_offset[e] = s; s += g_count[e]; }
    }
}

// ---------------- GEMM1 (mma.sync experiment): h1 = gelu(x_gathered @ w1 + b1) --
// CTA tile 128x128, k-chunk 16; 8 warps as 2(m) x 4(n), warp tile 64x32.
// SMEM layout: pair-packed u32 arrays [kp][m], kp = k/2 (0..7), row stride 136.
// Fragments loaded as scalar LDS.32 (no ldmatrix); loads via plain LDG (no cp.async).
// 3-product bf16 split (Ah*Bh + Ah*Bl + Al*Bh) with fp32 accumulators.
__global__ void __launch_bounds__(256)
gemm1_mma(const float* __restrict__ x,
          const float* __restrict__ w1,
          const float* __restrict__ b1) {
    int e = blockIdx.z, mt = blockIdx.y;
    int cnt = g_count[e];
    if (mt * 128 >= cnt) return;
    int nt = blockIdx.x;
    int off = g_offset[e];

    __shared__ uint32_t Ah[8][136], Al[8][136], Bh[8][136], Bl[8][136];
    __shared__ int rowtok[128];

    int tid = threadIdx.x, lane = tid & 31, wid = tid >> 5;
    int wm = wid & 1, wn = wid >> 1;
    int g = lane >> 2, tig = lane & 3;

    if (tid < 128) {
        int m = mt * 128 + tid;
        rowtok[tid] = (m < cnt) ? (g_pairs[e][m] >> 1) : -1;
    }
    __syncthreads();

    const float* w1e = w1 + (size_t)e * DDIM * FDIM + nt * 128;

    float2 aval[4];
    float  bv0[4], bv1[4];

    auto ldg_chunk = [&](int c) {
        int k0 = c * 16;
        #pragma unroll
        for (int it = 0; it < 4; it++) {
            int m = lane + 32 * it;
            int t = rowtok[m];
            float2 v = make_float2(0.f, 0.f);
            if (t >= 0) v = *(const float2*)(x + (size_t)t * DDIM + k0 + 2 * wid);
            aval[it] = v;
            const float* bp = w1e + (size_t)(k0 + 2 * wid) * FDIM + m;
            bv0[it] = bp[0];
            bv1[it] = bp[FDIM];
        }
    };
    auto sts_chunk = [&]() {
        #pragma unroll
        for (int it = 0; it < 4; it++) {
            int m = lane + 32 * it;
            Ah[wid][m] = pack_bf2(aval[it].x, aval[it].y);
            Al[wid][m] = pack_bf2(bres(aval[it].x), bres(aval[it].y));
            Bh[wid][m] = pack_bf2(bv0[it], bv1[it]);
            Bl[wid][m] = pack_bf2(bres(bv0[it]), bres(bv1[it]));
        }
    };

    float acc[4][4][4] = {};

    ldg_chunk(0);
    const int NCH = DDIM / 16;   // 64
    for (int c = 0; c < NCH; c++) {
        __syncthreads();
        sts_chunk();
        __syncthreads();
        if (c + 1 < NCH) ldg_chunk(c + 1);

        // B fragments for this warp's 4 n-tiles
        uint32_t fbh[4][2], fbl[4][2];
        #pragma unroll
        for (int t = 0; t < 4; t++) {
            int n = wn * 32 + t * 8 + g;
            fbh[t][0] = Bh[tig][n];     fbh[t][1] = Bh[tig + 4][n];
            fbl[t][0] = Bl[tig][n];     fbl[t][1] = Bl[tig + 4][n];
        }
        #pragma unroll
        for (int i = 0; i < 4; i++) {
            int m = wm * 64 + i * 16 + g;
            uint32_t a0 = Ah[tig][m],     a1 = Ah[tig][m + 8];
            uint32_t a2 = Ah[tig + 4][m], a3 = Ah[tig + 4][m + 8];
            uint32_t l0 = Al[tig][m],     l1 = Al[tig][m + 8];
            uint32_t l2 = Al[tig + 4][m], l3 = Al[tig + 4][m + 8];
            #pragma unroll
            for (int t = 0; t < 4; t++) {
                MMA_BF16(acc[i][t], a0, a1, a2, a3, fbh[t][0], fbh[t][1]);
                MMA_BF16(acc[i][t], a0, a1, a2, a3, fbl[t][0], fbl[t][1]);
                MMA_BF16(acc[i][t], l0, l1, l2, l3, fbh[t][0], fbh[t][1]);
            }
        }
    }

    // epilogue: bias + exact gelu, fp32 store to g_h1
    int lim = cnt - mt * 128; if (lim > 128) lim = 128;
    const float* b1e = b1 + (size_t)e * FDIM + nt * 128;
    #pragma unroll
    for (int i = 0; i < 4; i++) {
        #pragma unroll
        for (int t = 0; t < 4; t++) {
            int col = wn * 32 + t * 8 + tig * 2;
            float bA = b1e[col], bB = b1e[col + 1];
            #pragma unroll
            for (int half = 0; half < 2; half++) {
                int r = wm * 64 + i * 16 + g + half * 8;
                if (r < lim) {
                    float v0 = acc[i][t][half * 2 + 0] + bA;
                    float v1 = acc[i][t][half * 2 + 1] + bB;
                    v0 = 0.5f * v0 * (1.0f + erff(v0 * 0.70710678118654752440f));
                    v1 = 0.5f * v1 * (1.0f + erff(v1 * 0.70710678118654752440f));
                    *(float2*)&g_h1[off + mt * 128 + r][nt * 128 + col] =
                        make_float2(v0, v1);
                }
            }
        }
    }
}

// ---------------- shared chunk compute for FFMA gemm2 (R6-proven) --------------
__device__ __forceinline__ void compute_chunk(
    const float (*As)[128], const float (*Bs)[128],
    ull (&acc)[4][8], int m0, int n0)
{
    #pragma unroll
    for (int kk = 0; kk < 16; kk++) {
        ulonglong2 a01 = *(const ulonglong2*)&As[kk][m0];
        ulonglong2 a23 = *(const ulonglong2*)&As[kk][m0 + 4];
        ull a2[4] = { a01.x, a01.y, a23.x, a23.y };
        float4 bA = *(const float4*)&Bs[kk][n0];
        float4 bB = *(const float4*)&Bs[kk][n0 + 4];
        ull bb[8] = { bcast2(bA.x), bcast2(bA.y), bcast2(bA.z), bcast2(bA.w),
                      bcast2(bB.x), bcast2(bB.y), bcast2(bB.z), bcast2(bB.w) };
        #pragma unroll
        for (int i = 0; i < 4; i++)
            #pragma unroll
            for (int j = 0; j < 8; j++)
                fma2(acc[i][j], a2[i], bb[j]);
    }
}

// ---------------- GEMM2: out2 = h1 @ w2[e] + b2[e] (R6-proven FFMA path) -------
__global__ void __launch_bounds__(256)
gemm2_kernel(const float* __restrict__ w2,
             const float* __restrict__ b2) {
    int e = blockIdx.z, mt = blockIdx.y;
    int cnt = g_count[e];
    if (mt * 128 >= cnt) return;
    int nt = blockIdx.x;
    int off = g_offset[e];

    __shared__ float As[16][128];
    __shared__ float Bs[16][128];
    __shared__ int pid[128];

    int tid = threadIdx.x;
    int tx = tid & 15, ty = tid >> 4;
    int m0 = ty * 8, n0 = tx * 8;

    if (tid < 128) {
        int m = mt * 128 + tid;
        pid[tid] = (m < cnt) ? g_pairs[e][m] : -1;
    }

    int am = tid >> 1, aks = (tid & 1) * 8;
    int bk = tid >> 4, bi = tid & 15;
    const float* arow = g_h1[off + mt * 128 + am];
    const float* w2e = w2 + (size_t)e * FDIM * DDIM + nt * 128;

    ull acc[4][8] = {};
    float4 av0, av1, bu0, bu1;

    auto load_regs = [&](int k0) {
        const float4* src = (const float4*)(arow + k0 + aks);
        av0 = src[0]; av1 = src[1];
        const float4* wrow = (const float4*)(w2e + (size_t)(k0 + bk) * DDIM);
        bu0 = wrow[bi];
        bu1 = wrow[bi + 16];
    };
    auto store_smem = [&]() {
        As[aks + 0][am] = av0.x; As[aks + 1][am] = av0.y;
        As[aks + 2][am] = av0.z; As[aks + 3][am] = av0.w;
        As[aks + 4][am] = av1.x; As[aks + 5][am] = av1.y;
        As[aks + 6][am] = av1.z; As[aks + 7][am] = av1.w;
        *(float4*)&Bs[bk][bi * 4]      = bu0;
        *(float4*)&Bs[bk][bi * 4 + 64] = bu1;
    };

    load_regs(0);
    const int NCH = FDIM / 16;
    for (int c = 0; c < NCH; c++) {
        __syncthreads();
        store_smem();
        __syncthreads();
        if (c + 1 < NCH) load_regs((c + 1) * 16);
        compute_chunk(As, Bs, acc, m0, n0);
    }

    __syncthreads();
    int lim = cnt - mt * 128; if (lim > 128) lim = 128;
    const float* b2e = b2 + (size_t)e * DDIM + nt * 128 + n0;
    float bv[8];
    *(float4*)&bv[0] = *(const float4*)&b2e[0];
    *(float4*)&bv[4] = *(const float4*)&b2e[4];
    #pragma unroll
    for (int i = 0; i < 4; i++) {
        float lo[8], hi[8];
        #pragma unroll
        for (int j = 0; j < 8; j++) unpack2(acc[i][j], lo[j], hi[j]);
        #pragma unroll
        for (int h = 0; h < 2; h++) {
            int r = m0 + i * 2 + h;
            if (r < lim) {
                int pr = pid[r];
                float* dst = &g_out2[pr][nt * 128 + n0];
                float o[8];
                #pragma unroll
                for (int j = 0; j < 8; j++) o[j] = (h ? hi[j] : lo[j]) + bv[j];
                *(float4*)&dst[0] = *(float4*)&o[0];
                *(float4*)&dst[4] = *(float4*)&o[4];
            }
        }
    }
}

// ---------------- combine: out = clip(x + w0*o0 + w1*o1, +-100) -----------------
__global__ void combine_kernel(const float* __restrict__ x,
                               float* __restrict__ out) {
    int i = blockIdx.x * 256 + threadIdx.x;
    int n = i >> 10;
    int d = i & 1023;
    float v = x[i]
            + g_gatew[n][0] * g_out2[2 * n + 0][d]
            + g_gatew[n][1] * g_out2[2 * n + 1][d];
    out[i] = fminf(fmaxf(v, -100.0f), 100.0f);
}

// ---------------- launch --------------------------------------------------------
extern "C" void kernel_launch(void* const* d_in, const int* in_sizes, int n_in,
                              void* d_out, int out_size) {
    const float* h      = (const float*)d_in[0];   // (2,1024,1024)
    const float* gate_w = (const float*)d_in[1];   // (14,1024)
    const float* w1     = (const float*)d_in[2];   // (14,1024,2048)
    const float* b1     = (const float*)d_in[3];   // (14,2048)
    const float* w2     = (const float*)d_in[4];   // (14,2048,1024)
    const float* b2     = (const float*)d_in[5];   // (14,1024)
    float* out = (float*)d_out;

    zero_kernel<<<1, 32>>>();
    gate_kernel<<<NTOK, 128>>>(h, gate_w);
    prefix_kernel<<<1, 32>>>();
    gemm1_mma<<<dim3(FDIM / 128, NTOK / 128, NEXP), 256>>>(h, w1, b1);
    gemm2_kernel<<<dim3(DDIM / 128, NTOK / 128, NEXP), 256>>>(w2, b2);
    combine_kernel<<<(NTOK * DDIM) / 256, 256>>>(h, out);
}

// round 8
// speedup vs baseline: 1.5069x; 1.1988x over previous
#include <cuda_runtime.h>
#include <math.h>
#include <stdint.h>
#include <cuda_bf16.h>

#define NTOK 2048
#define DDIM 1024
#define NEXP 14
#define FDIM 2048
#define NPAIR (2*NTOK)
#define MPAD  (NPAIR + 128)

// ---------------- device scratch ---------------------------------------------
__device__ int   g_count[NEXP];
__device__ int   g_offset[NEXP];
__device__ int   g_pairs[NEXP][NTOK];      // value = token*2 + slot
__device__ float g_gatew[NTOK][2];
__device__ float g_h1[MPAD][FDIM];         // gemm1 output, row = offset[e]+m
__device__ float g_out2[NPAIR][DDIM];      // gemm2 output, row = pair id

// ---------------- bf16 split helpers -------------------------------------------
__device__ __forceinline__ uint32_t pack_bf2(float a, float b) {
    __nv_bfloat162 t = __floats2bfloat162_rn(a, b);
    return *reinterpret_cast<uint32_t*>(&t);
}
__device__ __forceinline__ float bres(float v) {
    return v - __bfloat162float(__float2bfloat16_rn(v));
}

#define MMA_BF16(d, a0, a1, a2, a3, b0, b1) \
    asm volatile("mma.sync.aligned.m16n8k16.row.col.f32.bf16.bf16.f32 " \
        "{%0,%1,%2,%3},{%4,%5,%6,%7},{%8,%9},{%0,%1,%2,%3};" \
        : "+f"((d)[0]), "+f"((d)[1]), "+f"((d)[2]), "+f"((d)[3]) \
        : "r"(a0), "r"(a1), "r"(a2), "r"(a3), "r"(b0), "r"(b1))

// ---------------- kernel: zero expert counts ----------------------------------
__global__ void zero_kernel() {
    if (threadIdx.x < NEXP) g_count[threadIdx.x] = 0;
}

// ---------------- kernel: gating (proven) ---------------------------------------
__global__ void gate_kernel(const float* __restrict__ x,
                            const float* __restrict__ gw) {
    int n = blockIdx.x;
    __shared__ float sx[DDIM];
    __shared__ float red[128];
    __shared__ float logits[NEXP];
    const float* xr = x + (size_t)n * DDIM;
    for (int d = threadIdx.x; d < DDIM; d += 128) sx[d] = xr[d];
    __syncthreads();
    for (int e = 0; e < NEXP; e++) {
        const float* w = gw + (size_t)e * DDIM;
        float s = 0.f;
        for (int d = threadIdx.x; d < DDIM; d += 128) s += sx[d] * w[d];
        red[threadIdx.x] = s;
        __syncthreads();
        #pragma unroll
        for (int st = 64; st > 0; st >>= 1) {
            if (threadIdx.x < st) red[threadIdx.x] += red[threadIdx.x + st];
            __syncthreads();
        }
        if (threadIdx.x == 0) logits[e] = red[0];
        __syncthreads();
    }
    if (threadIdx.x == 0) {
        int i0 = 0; float l0 = logits[0];
        for (int e = 1; e < NEXP; e++) if (logits[e] > l0) { l0 = logits[e]; i0 = e; }
        int i1 = -1; float l1 = -3.0e38f;
        for (int e = 0; e < NEXP; e++) if (e != i0 && logits[e] > l1) { l1 = logits[e]; i1 = e; }
        float p1 = expf(l1 - l0);
        float inv = 1.0f / (1.0f + p1);
        g_gatew[n][0] = inv;
        g_gatew[n][1] = p1 * inv;
        int s0 = atomicAdd(&g_count[i0], 1);
        g_pairs[i0][s0] = n * 2 + 0;
        int s1 = atomicAdd(&g_count[i1], 1);
        g_pairs[i1][s1] = n * 2 + 1;
    }
}

__global__ void prefix_kernel() {
    if (threadIdx.x == 0) {
        int s = 0;
        for (int e = 0; e < NEXP; e++) { g_offset[e] = s; s += g_count[e]; }
    }
}

// ---------------- GEMM1 (mma, double-buffered): h1 = gelu(x@w1 + b1) -----------
// CTA tile 128x128, k-chunk 16; 8 warps as 2(m) x 4(n), warp tile 64x32.
// SMEM: pair-packed u32 [buf][kp][m], kp=k/2, row stride 136 (conflict-free).
// 3-product bf16 split, fp32 accumulate. Plain LDG; no cp.async/ldmatrix.
__global__ void __launch_bounds__(256)
gemm1_mma(const float* __restrict__ x,
          const float* __restrict__ w1,
          const float* __restrict__ b1) {
    int e = blockIdx.z, mt = blockIdx.y;
    int cnt = g_count[e];
    if (mt * 128 >= cnt) return;
    int nt = blockIdx.x;
    int off = g_offset[e];

    __shared__ uint32_t Ah[2][8][136], Al[2][8][136], Bh[2][8][136], Bl[2][8][136];
    __shared__ int rowtok[128];

    int tid = threadIdx.x, lane = tid & 31, wid = tid >> 5;
    int wm = wid & 1, wn = wid >> 1;
    int g = lane >> 2, tig = lane & 3;

    if (tid < 128) {
        int m = mt * 128 + tid;
        rowtok[tid] = (m < cnt) ? (g_pairs[e][m] >> 1) : -1;
    }
    __syncthreads();

    const float* w1e = w1 + (size_t)e * DDIM * FDIM + nt * 128;

    float2 aval[4];
    float  bv0[4], bv1[4];

    auto ldg_chunk = [&](int c) {
        int k0 = c * 16;
        #pragma unroll
        for (int it = 0; it < 4; it++) {
            int m = lane + 32 * it;
            int t = rowtok[m];
            float2 v = make_float2(0.f, 0.f);
            if (t >= 0) v = *(const float2*)(x + (size_t)t * DDIM + k0 + 2 * wid);
            aval[it] = v;
            const float* bp = w1e + (size_t)(k0 + 2 * wid) * FDIM + m;
            bv0[it] = bp[0];
            bv1[it] = bp[FDIM];
        }
    };
    auto sts_chunk = [&](int buf) {
        #pragma unroll
        for (int it = 0; it < 4; it++) {
            int m = lane + 32 * it;
            Ah[buf][wid][m] = pack_bf2(aval[it].x, aval[it].y);
            Al[buf][wid][m] = pack_bf2(bres(aval[it].x), bres(aval[it].y));
            Bh[buf][wid][m] = pack_bf2(bv0[it], bv1[it]);
            Bl[buf][wid][m] = pack_bf2(bres(bv0[it]), bres(bv1[it]));
        }
    };

    float acc[4][4][4] = {};

    ldg_chunk(0);
    sts_chunk(0);
    __syncthreads();

    const int NCH = DDIM / 16;   // 64
    for (int c = 0; c < NCH; c++) {
        int buf = c & 1;
        if (c + 1 < NCH) ldg_chunk(c + 1);

        uint32_t fbh[4][2], fbl[4][2];
        #pragma unroll
        for (int t = 0; t < 4; t++) {
            int n = wn * 32 + t * 8 + g;
            fbh[t][0] = Bh[buf][tig][n];     fbh[t][1] = Bh[buf][tig + 4][n];
            fbl[t][0] = Bl[buf][tig][n];     fbl[t][1] = Bl[buf][tig + 4][n];
        }
        #pragma unroll
        for (int i = 0; i < 4; i++) {
            int m = wm * 64 + i * 16 + g;
            uint32_t a0 = Ah[buf][tig][m],     a1 = Ah[buf][tig][m + 8];
            uint32_t a2 = Ah[buf][tig + 4][m], a3 = Ah[buf][tig + 4][m + 8];
            uint32_t l0 = Al[buf][tig][m],     l1 = Al[buf][tig][m + 8];
            uint32_t l2 = Al[buf][tig + 4][m], l3 = Al[buf][tig + 4][m + 8];
            #pragma unroll
            for (int t = 0; t < 4; t++) {
                MMA_BF16(acc[i][t], a0, a1, a2, a3, fbh[t][0], fbh[t][1]);
                MMA_BF16(acc[i][t], a0, a1, a2, a3, fbl[t][0], fbl[t][1]);
                MMA_BF16(acc[i][t], l0, l1, l2, l3, fbh[t][0], fbh[t][1]);
            }
        }
        if (c + 1 < NCH) sts_chunk((c + 1) & 1);
        __syncthreads();
    }

    // epilogue: bias + exact gelu, fp32 store to g_h1
    int lim = cnt - mt * 128; if (lim > 128) lim = 128;
    const float* b1e = b1 + (size_t)e * FDIM + nt * 128;
    #pragma unroll
    for (int i = 0; i < 4; i++) {
        #pragma unroll
        for (int t = 0; t < 4; t++) {
            int col = wn * 32 + t * 8 + tig * 2;
            float bA = b1e[col], bB = b1e[col + 1];
            #pragma unroll
            for (int half = 0; half < 2; half++) {
                int r = wm * 64 + i * 16 + g + half * 8;
                if (r < lim) {
                    float v0 = acc[i][t][half * 2 + 0] + bA;
                    float v1 = acc[i][t][half * 2 + 1] + bB;
                    v0 = 0.5f * v0 * (1.0f + erff(v0 * 0.70710678118654752440f));
                    v1 = 0.5f * v1 * (1.0f + erff(v1 * 0.70710678118654752440f));
                    *(float2*)&g_h1[off + mt * 128 + r][nt * 128 + col] =
                        make_float2(v0, v1);
                }
            }
        }
    }
}

// ---------------- GEMM2 (mma, double-buffered): out2 = h1 @ w2 + b2 ------------
__global__ void __launch_bounds__(256)
gemm2_mma(const float* __restrict__ w2,
          const float* __restrict__ b2) {
    int e = blockIdx.z, mt = blockIdx.y;
    int cnt = g_count[e];
    if (mt * 128 >= cnt) return;
    int nt = blockIdx.x;
    int off = g_offset[e];
    int mrow0 = off + mt * 128;

    __shared__ uint32_t Ah[2][8][136], Al[2][8][136], Bh[2][8][136], Bl[2][8][136];
    __shared__ int pid[128];

    int tid = threadIdx.x, lane = tid & 31, wid = tid >> 5;
    int wm = wid & 1, wn = wid >> 1;
    int g = lane >> 2, tig = lane & 3;

    if (tid < 128) {
        int m = mt * 128 + tid;
        pid[tid] = (m < cnt) ? g_pairs[e][m] : 0;
    }
    __syncthreads();

    const float* w2e = w2 + (size_t)e * FDIM * DDIM + nt * 128;

    float2 aval[4];
    float  bv0[4], bv1[4];

    auto ldg_chunk = [&](int c) {
        int k0 = c * 16;
        #pragma unroll
        for (int it = 0; it < 4; it++) {
            int m = lane + 32 * it;
            aval[it] = *(const float2*)(&g_h1[mrow0 + m][k0 + 2 * wid]);
            const float* bp = w2e + (size_t)(k0 + 2 * wid) * DDIM + m;
            bv0[it] = bp[0];
            bv1[it] = bp[DDIM];
        }
    };
    auto sts_chunk = [&](int buf) {
        #pragma unroll
        for (int it = 0; it < 4; it++) {
            int m = lane + 32 * it;
            Ah[buf][wid][m] = pack_bf2(aval[it].x, aval[it].y);
            Al[buf][wid][m] = pack_bf2(bres(aval[it].x), bres(aval[it].y));
            Bh[buf][wid][m] = pack_bf2(bv0[it], bv1[it]);
            Bl[buf][wid][m] = pack_bf2(bres(bv0[it]), bres(bv1[it]));
        }
    };

    float acc[4][4][4] = {};

    ldg_chunk(0);
    sts_chunk(0);
    __syncthreads();

    const int NCH = FDIM / 16;   // 128
    for (int c = 0; c < NCH; c++) {
        int buf = c & 1;
        if (c + 1 < NCH) ldg_chunk(c + 1);

        uint32_t fbh[4][2], fbl[4][2];
        #pragma unroll
        for (int t = 0; t < 4; t++) {
            int n = wn * 32 + t * 8 + g;
            fbh[t][0] = Bh[buf][tig][n];     fbh[t][1] = Bh[buf][tig + 4][n];
            fbl[t][0] = Bl[buf][tig][n];     fbl[t][1] = Bl[buf][tig + 4][n];
        }
        #pragma unroll
        for (int i = 0; i < 4; i++) {
            int m = wm * 64 + i * 16 + g;
            uint32_t a0 = Ah[buf][tig][m],     a1 = Ah[buf][tig][m + 8];
            uint32_t a2 = Ah[buf][tig + 4][m], a3 = Ah[buf][tig + 4][m + 8];
            uint32_t l0 = Al[buf][tig][m],     l1 = Al[buf][tig][m + 8];
            uint32_t l2 = Al[buf][tig + 4][m], l3 = Al[buf][tig + 4][m + 8];
            #pragma unroll
            for (int t = 0; t < 4; t++) {
                MMA_BF16(acc[i][t], a0, a1, a2, a3, fbh[t][0], fbh[t][1]);
                MMA_BF16(acc[i][t], a0, a1, a2, a3, fbl[t][0], fbl[t][1]);
                MMA_BF16(acc[i][t], l0, l1, l2, l3, fbh[t][0], fbh[t][1]);
            }
        }
        if (c + 1 < NCH) sts_chunk((c + 1) & 1);
        __syncthreads();
    }

    // epilogue: bias, scatter rows by pair id
    int lim = cnt - mt * 128; if (lim > 128) lim = 128;
    const float* b2e = b2 + (size_t)e * DDIM + nt * 128;
    #pragma unroll
    for (int i = 0; i < 4; i++) {
        #pragma unroll
        for (int t = 0; t < 4; t++) {
            int col = wn * 32 + t * 8 + tig * 2;
            float bA = b2e[col], bB = b2e[col + 1];
            #pragma unroll
            for (int half = 0; half < 2; half++) {
                int r = wm * 64 + i * 16 + g + half * 8;
                if (r < lim) {
                    int pr = pid[r];
                    *(float2*)&g_out2[pr][nt * 128 + col] =
                        make_float2(acc[i][t][half * 2 + 0] + bA,
                                    acc[i][t][half * 2 + 1] + bB);
                }
            }
        }
    }
}

// ---------------- combine: out = clip(x + w0*o0 + w1*o1, +-100) -----------------
__global__ void combine_kernel(const float* __restrict__ x,
                               float* __restrict__ out) {
    int i = blockIdx.x * 256 + threadIdx.x;
    int n = i >> 10;
    int d = i & 1023;
    float v = x[i]
            + g_gatew[n][0] * g_out2[2 * n + 0][d]
            + g_gatew[n][1] * g_out2[2 * n + 1][d];
    out[i] = fminf(fmaxf(v, -100.0f), 100.0f);
}

// ---------------- launch --------------------------------------------------------
extern "C" void kernel_launch(void* const* d_in, const int* in_sizes, int n_in,
                              void* d_out, int out_size) {
    const float* h      = (const float*)d_in[0];   // (2,1024,1024)
    const float* gate_w = (const float*)d_in[1];   // (14,1024)
    const float* w1     = (const float*)d_in[2];   // (14,1024,2048)
    const float* b1     = (const float*)d_in[3];   // (14,2048)
    const float* w2     = (const float*)d_in[4];   // (14,2048,1024)
    const float* b2     = (const float*)d_in[5];   // (14,1024)
    float* out = (float*)d_out;

    zero_kernel<<<1, 32>>>();
    gate_kernel<<<NTOK, 128>>>(h, gate_w);
    prefix_kernel<<<1, 32>>>();
    gemm1_mma<<<dim3(FDIM / 128, NTOK / 128, NEXP), 256>>>(h, w1, b1);
    gemm2_mma<<<dim3(DDIM / 128, NTOK / 128, NEXP), 256>>>(w2, b2);
    combine_kernel<<<(NTOK * DDIM) / 256, 256>>>(h, out);
}

// round 9
// speedup vs baseline: 1.8547x; 1.2308x over previous
#include <cuda_runtime.h>
#include <math.h>
#include <stdint.h>
#include <cuda_bf16.h>

#define NTOK 2048
#define DDIM 1024
#define NEXP 14
#define FDIM 2048
#define NPAIR (2*NTOK)
#define MPAD  (NPAIR + 128)

// ---------------- device scratch ---------------------------------------------
__device__ int   g_count[NEXP];
__device__ int   g_offset[NEXP];
__device__ int   g_pairs[NEXP][NTOK];      // value = token*2 + slot
__device__ float g_gatew[NTOK][2];
__device__ float g_h1[MPAD][FDIM];         // gemm1 output, row = offset[e]+m
__device__ float g_out2[NPAIR][DDIM];      // gemm2 output, row = pair id

// ---------------- bf16 split helpers -------------------------------------------
__device__ __forceinline__ uint32_t pack_bf2(float a, float b) {
    __nv_bfloat162 t = __floats2bfloat162_rn(a, b);
    return *reinterpret_cast<uint32_t*>(&t);
}
__device__ __forceinline__ float bres(float v) {
    return v - __bfloat162float(__float2bfloat16_rn(v));
}
__device__ __forceinline__ uint32_t smem_u32(const void* p) {
    uint32_t a;
    asm("{ .reg .u64 t; cvta.to.shared.u64 t, %1; cvt.u32.u64 %0, t; }" : "=r"(a) : "l"(p));
    return a;
}

#define MMA_BF16(d, a, b0, b1) \
    asm volatile("mma.sync.aligned.m16n8k16.row.col.f32.bf16.bf16.f32 " \
        "{%0,%1,%2,%3},{%4,%5,%6,%7},{%8,%9},{%0,%1,%2,%3};" \
        : "+f"((d)[0]), "+f"((d)[1]), "+f"((d)[2]), "+f"((d)[3]) \
        : "r"((a)[0]), "r"((a)[1]), "r"((a)[2]), "r"((a)[3]), "r"(b0), "r"(b1))

#define LDSM4(r, addr) \
    asm volatile("ldmatrix.sync.aligned.m8n8.x4.shared.b16 {%0,%1,%2,%3}, [%4];" \
        : "=r"((r)[0]), "=r"((r)[1]), "=r"((r)[2]), "=r"((r)[3]) : "r"(addr))

// ---------------- kernel: zero expert counts ----------------------------------
__global__ void zero_kernel() {
    if (threadIdx.x < NEXP) g_count[threadIdx.x] = 0;
}

// ---------------- kernel: gating (proven) ---------------------------------------
__global__ void gate_kernel(const float* __restrict__ x,
                            const float* __restrict__ gw) {
    int n = blockIdx.x;
    __shared__ float sx[DDIM];
    __shared__ float red[128];
    __shared__ float logits[NEXP];
    const float* xr = x + (size_t)n * DDIM;
    for (int d = threadIdx.x; d < DDIM; d += 128) sx[d] = xr[d];
    __syncthreads();
    for (int e = 0; e < NEXP; e++) {
        const float* w = gw + (size_t)e * DDIM;
        float s = 0.f;
        for (int d = threadIdx.x; d < DDIM; d += 128) s += sx[d] * w[d];
        red[threadIdx.x] = s;
        __syncthreads();
        #pragma unroll
        for (int st = 64; st > 0; st >>= 1) {
            if (threadIdx.x < st) red[threadIdx.x] += red[threadIdx.x + st];
            __syncthreads();
        }
        if (threadIdx.x == 0) logits[e] = red[0];
        __syncthreads();
    }
    if (threadIdx.x == 0) {
        int i0 = 0; float l0 = logits[0];
        for (int e = 1; e < NEXP; e++) if (logits[e] > l0) { l0 = logits[e]; i0 = e; }
        int i1 = -1; float l1 = -3.0e38f;
        for (int e = 0; e < NEXP; e++) if (e != i0 && logits[e] > l1) { l1 = logits[e]; i1 = e; }
        float p1 = expf(l1 - l0);
        float inv = 1.0f / (1.0f + p1);
        g_gatew[n][0] = inv;
        g_gatew[n][1] = p1 * inv;
        int s0 = atomicAdd(&g_count[i0], 1);
        g_pairs[i0][s0] = n * 2 + 0;
        int s1 = atomicAdd(&g_count[i1], 1);
        g_pairs[i1][s1] = n * 2 + 1;
    }
}

__global__ void prefix_kernel() {
    if (threadIdx.x == 0) {
        int s = 0;
        for (int e = 0; e < NEXP; e++) { g_offset[e] = s; s += g_count[e]; }
    }
}

// =================================================================================
// GEMM mainloop common layout:
//   S[0]=Ah, S[1]=Al, S[2]=Bh, S[3]=Bl : each [128 rows][12 u32] (48B row stride)
//   row m/n holds 16 bf16 of k: u32[0..3]=k0-7, u32[4..7]=k8-15, u32[8..11]=pad
//   8 warps = 2(m) x 4(n); warp tile 64x32; 3-product bf16 split, fp32 accum.
//   Fragments via ldmatrix.x4; loads via plain LDG (single-buffer, R7 schedule).
// =================================================================================

// ---------------- GEMM1: h1 = gelu(x_gathered @ w1 + b1) -------------------------
__global__ void __launch_bounds__(256, 2)
gemm1_mma(const float* __restrict__ x,
          const float* __restrict__ w1,
          const float* __restrict__ b1) {
    int e = blockIdx.z, mt = blockIdx.y;
    int cnt = g_count[e];
    if (mt * 128 >= cnt) return;
    int nt = blockIdx.x;
    int off = g_offset[e];

    __shared__ uint32_t S[4][128][12];
    __shared__ int rowtok[128];

    int tid = threadIdx.x, lane = tid & 31, wid = tid >> 5;
    int wm = wid & 1, wn = wid >> 1;
    int g = lane >> 2, tig = lane & 3;

    if (tid < 128) {
        int m = mt * 128 + tid;
        rowtok[tid] = (m < cnt) ? (g_pairs[e][m] >> 1) : -1;
    }
    __syncthreads();

    // loader mapping: lm = row (A) / col (B), kh = k-half
    int lm = tid & 127, kh = tid >> 7;
    int tok = rowtok[lm];
    const float* w1e = w1 + (size_t)e * DDIM * FDIM + nt * 128;
    const float* xrow = x + (size_t)(tok < 0 ? 0 : tok) * DDIM + kh * 8;
    const float* bcol = w1e + (size_t)kh * 8 * FDIM + lm;

    float fa[8], fb[8];
    auto ldg_chunk = [&](int c) {
        int k0 = c * 16;
        float4 u0 = make_float4(0.f, 0.f, 0.f, 0.f), u1 = u0;
        if (tok >= 0) {
            u0 = *(const float4*)(xrow + k0);
            u1 = *(const float4*)(xrow + k0 + 4);
        }
        fa[0] = u0.x; fa[1] = u0.y; fa[2] = u0.z; fa[3] = u0.w;
        fa[4] = u1.x; fa[5] = u1.y; fa[6] = u1.z; fa[7] = u1.w;
        const float* bp = bcol + (size_t)k0 * FDIM;
        #pragma unroll
        for (int j = 0; j < 8; j++) fb[j] = bp[(size_t)j * FDIM];
    };
    auto sts_chunk = [&]() {
        uint4 hv, lv;
        hv = make_uint4(pack_bf2(fa[0], fa[1]), pack_bf2(fa[2], fa[3]),
                        pack_bf2(fa[4], fa[5]), pack_bf2(fa[6], fa[7]));
        lv = make_uint4(pack_bf2(bres(fa[0]), bres(fa[1])), pack_bf2(bres(fa[2]), bres(fa[3])),
                        pack_bf2(bres(fa[4]), bres(fa[5])), pack_bf2(bres(fa[6]), bres(fa[7])));
        *(uint4*)&S[0][lm][kh * 4] = hv;
        *(uint4*)&S[1][lm][kh * 4] = lv;
        hv = make_uint4(pack_bf2(fb[0], fb[1]), pack_bf2(fb[2], fb[3]),
                        pack_bf2(fb[4], fb[5]), pack_bf2(fb[6], fb[7]));
        lv = make_uint4(pack_bf2(bres(fb[0]), bres(fb[1])), pack_bf2(bres(fb[2]), bres(fb[3])),
                        pack_bf2(bres(fb[4]), bres(fb[5])), pack_bf2(bres(fb[6]), bres(fb[7])));
        *(uint4*)&S[2][lm][kh * 4] = hv;
        *(uint4*)&S[3][lm][kh * 4] = lv;
    };

    // ldmatrix per-lane addresses
    uint32_t sbase = smem_u32(&S[0][0][0]);
    uint32_t aA = sbase + (((wm * 64 + (lane & 15)) * 12) + (lane >> 4) * 4) * 4;
    uint32_t aB = sbase + 2 * 6144
                + (((wn * 32 + ((lane >> 4) << 3) + (lane & 7)) * 12) + ((lane >> 3) & 1) * 4) * 4;

    float acc[4][4][4] = {};

    ldg_chunk(0);
    const int NCH = DDIM / 16;   // 64
    for (int c = 0; c < NCH; c++) {
        __syncthreads();
        sts_chunk();
        __syncthreads();
        if (c + 1 < NCH) ldg_chunk(c + 1);

        uint32_t bh01[4], bh23[4], bl01[4], bl23[4];
        LDSM4(bh01, aB);               // t0: r0,r1  t1: r2,r3
        LDSM4(bh23, aB + 768);         // t2, t3
        LDSM4(bl01, aB + 6144);
        LDSM4(bl23, aB + 6144 + 768);
        #pragma unroll
        for (int i = 0; i < 4; i++) {
            uint32_t ah[4], al[4];
            LDSM4(ah, aA + i * 768);
            LDSM4(al, aA + 6144 + i * 768);
            MMA_BF16(acc[i][0], ah, bh01[0], bh01[1]);
            MMA_BF16(acc[i][0], ah, bl01[0], bl01[1]);
            MMA_BF16(acc[i][0], al, bh01[0], bh01[1]);
            MMA_BF16(acc[i][1], ah, bh01[2], bh01[3]);
            MMA_BF16(acc[i][1], ah, bl01[2], bl01[3]);
            MMA_BF16(acc[i][1], al, bh01[2], bh01[3]);
            MMA_BF16(acc[i][2], ah, bh23[0], bh23[1]);
            MMA_BF16(acc[i][2], ah, bl23[0], bl23[1]);
            MMA_BF16(acc[i][2], al, bh23[0], bh23[1]);
            MMA_BF16(acc[i][3], ah, bh23[2], bh23[3]);
            MMA_BF16(acc[i][3], ah, bl23[2], bl23[3]);
            MMA_BF16(acc[i][3], al, bh23[2], bh23[3]);
        }
    }

    // epilogue: bias + exact gelu, fp32 store to g_h1
    int lim = cnt - mt * 128; if (lim > 128) lim = 128;
    const float* b1e = b1 + (size_t)e * FDIM + nt * 128;
    #pragma unroll
    for (int i = 0; i < 4; i++) {
        #pragma unroll
        for (int t = 0; t < 4; t++) {
            int col = wn * 32 + t * 8 + tig * 2;
            float bA = b1e[col], bB = b1e[col + 1];
            #pragma unroll
            for (int half = 0; half < 2; half++) {
                int r = wm * 64 + i * 16 + g + half * 8;
                if (r < lim) {
                    float v0 = acc[i][t][half * 2 + 0] + bA;
                    float v1 = acc[i][t][half * 2 + 1] + bB;
                    v0 = 0.5f * v0 * (1.0f + erff(v0 * 0.70710678118654752440f));
                    v1 = 0.5f * v1 * (1.0f + erff(v1 * 0.70710678118654752440f));
                    *(float2*)&g_h1[off + mt * 128 + r][nt * 128 + col] =
                        make_float2(v0, v1);
                }
            }
        }
    }
}

// ---------------- GEMM2: out2 = h1 @ w2 + b2, scatter by pair id -----------------
__global__ void __launch_bounds__(256, 2)
gemm2_mma(const float* __restrict__ w2,
          const float* __restrict__ b2) {
    int e = blockIdx.z, mt = blockIdx.y;
    int cnt = g_count[e];
    if (mt * 128 >= cnt) return;
    int nt = blockIdx.x;
    int off = g_offset[e];
    int mrow0 = off + mt * 128;

    __shared__ uint32_t S[4][128][12];
    __shared__ int pid[128];

    int tid = threadIdx.x, lane = tid & 31, wid = tid >> 5;
    int wm = wid & 1, wn = wid >> 1;
    int g = lane >> 2, tig = lane & 3;

    if (tid < 128) {
        int m = mt * 128 + tid;
        pid[tid] = (m < cnt) ? g_pairs[e][m] : 0;
    }
    __syncthreads();

    int lm = tid & 127, kh = tid >> 7;
    const float* w2e = w2 + (size_t)e * FDIM * DDIM + nt * 128;
    const float* arow = &g_h1[mrow0 + lm][kh * 8];
    const float* bcol = w2e + (size_t)kh * 8 * DDIM + lm;

    float fa[8], fb[8];
    auto ldg_chunk = [&](int c) {
        int k0 = c * 16;
        float4 u0 = *(const float4*)(arow + k0);
        float4 u1 = *(const float4*)(arow + k0 + 4);
        fa[0] = u0.x; fa[1] = u0.y; fa[2] = u0.z; fa[3] = u0.w;
        fa[4] = u1.x; fa[5] = u1.y; fa[6] = u1.z; fa[7] = u1.w;
        const float* bp = bcol + (size_t)k0 * DDIM;
        #pragma unroll
        for (int j = 0; j < 8; j++) fb[j] = bp[(size_t)j * DDIM];
    };
    auto sts_chunk = [&]() {
        uint4 hv, lv;
        hv = make_uint4(pack_bf2(fa[0], fa[1]), pack_bf2(fa[2], fa[3]),
                        pack_bf2(fa[4], fa[5]), pack_bf2(fa[6], fa[7]));
        lv = make_uint4(pack_bf2(bres(fa[0]), bres(fa[1])), pack_bf2(bres(fa[2]), bres(fa[3])),
                        pack_bf2(bres(fa[4]), bres(fa[5])), pack_bf2(bres(fa[6]), bres(fa[7])));
        *(uint4*)&S[0][lm][kh * 4] = hv;
        *(uint4*)&S[1][lm][kh * 4] = lv;
        hv = make_uint4(pack_bf2(fb[0], fb[1]), pack_bf2(fb[2], fb[3]),
                        pack_bf2(fb[4], fb[5]), pack_bf2(fb[6], fb[7]));
        lv = make_uint4(pack_bf2(bres(fb[0]), bres(fb[1])), pack_bf2(bres(fb[2]), bres(fb[3])),
                        pack_bf2(bres(fb[4]), bres(fb[5])), pack_bf2(bres(fb[6]), bres(fb[7])));
        *(uint4*)&S[2][lm][kh * 4] = hv;
        *(uint4*)&S[3][lm][kh * 4] = lv;
    };

    uint32_t sbase = smem_u32(&S[0][0][0]);
    uint32_t aA = sbase + (((wm * 64 + (lane & 15)) * 12) + (lane >> 4) * 4) * 4;
    uint32_t aB = sbase + 2 * 6144
                + (((wn * 32 + ((lane >> 4) << 3) + (lane & 7)) * 12) + ((lane >> 3) & 1) * 4) * 4;

    float acc[4][4][4] = {};

    ldg_chunk(0);
    const int NCH = FDIM / 16;   // 128
    for (int c = 0; c < NCH; c++) {
        __syncthreads();
        sts_chunk();
        __syncthreads();
        if (c + 1 < NCH) ldg_chunk(c + 1);

        uint32_t bh01[4], bh23[4], bl01[4], bl23[4];
        LDSM4(bh01, aB);
        LDSM4(bh23, aB + 768);
        LDSM4(bl01, aB + 6144);
        LDSM4(bl23, aB + 6144 + 768);
        #pragma unroll
        for (int i = 0; i < 4; i++) {
            uint32_t ah[4], al[4];
            LDSM4(ah, aA + i * 768);
            LDSM4(al, aA + 6144 + i * 768);
            MMA_BF16(acc[i][0], ah, bh01[0], bh01[1]);
            MMA_BF16(acc[i][0], ah, bl01[0], bl01[1]);
            MMA_BF16(acc[i][0], al, bh01[0], bh01[1]);
            MMA_BF16(acc[i][1], ah, bh01[2], bh01[3]);
            MMA_BF16(acc[i][1], ah, bl01[2], bl01[3]);
            MMA_BF16(acc[i][1], al, bh01[2], bh01[3]);
            MMA_BF16(acc[i][2], ah, bh23[0], bh23[1]);
            MMA_BF16(acc[i][2], ah, bl23[0], bl23[1]);
            MMA_BF16(acc[i][2], al, bh23[0], bh23[1]);
            MMA_BF16(acc[i][3], ah, bh23[2], bh23[3]);
            MMA_BF16(acc[i][3], ah, bl23[2], bl23[3]);
            MMA_BF16(acc[i][3], al, bh23[2], bh23[3]);
        }
    }

    // epilogue: bias, scatter rows by pair id
    int lim = cnt - mt * 128; if (lim > 128) lim = 128;
    const float* b2e = b2 + (size_t)e * DDIM + nt * 128;
    #pragma unroll
    for (int i = 0; i < 4; i++) {
        #pragma unroll
        for (int t = 0; t < 4; t++) {
            int col = wn * 32 + t * 8 + tig * 2;
            float bA = b2e[col], bB = b2e[col + 1];
            #pragma unroll
            for (int half = 0; half < 2; half++) {
                int r = wm * 64 + i * 16 + g + half * 8;
                if (r < lim) {
                    int pr = pid[r];
                    *(float2*)&g_out2[pr][nt * 128 + col] =
                        make_float2(acc[i][t][half * 2 + 0] + bA,
                                    acc[i][t][half * 2 + 1] + bB);
                }
            }
        }
    }
}

// ---------------- combine: out = clip(x + w0*o0 + w1*o1, +-100) -----------------
__global__ void combine_kernel(const float* __restrict__ x,
                               float* __restrict__ out) {
    int i = blockIdx.x * 256 + threadIdx.x;
    int n = i >> 10;
    int d = i & 1023;
    float v = x[i]
            + g_gatew[n][0] * g_out2[2 * n + 0][d]
            + g_gatew[n][1] * g_out2[2 * n + 1][d];
    out[i] = fminf(fmaxf(v, -100.0f), 100.0f);
}

// ---------------- launch --------------------------------------------------------
extern "C" void kernel_launch(void* const* d_in, const int* in_sizes, int n_in,
                              void* d_out, int out_size) {
    const float* h      = (const float*)d_in[0];   // (2,1024,1024)
    const float* gate_w = (const float*)d_in[1];   // (14,1024)
    const float* w1     = (const float*)d_in[2];   // (14,1024,2048)
    const float* b1     = (const float*)d_in[3];   // (14,2048)
    const float* w2     = (const float*)d_in[4];   // (14,2048,1024)
    const float* b2     = (const float*)d_in[5];   // (14,1024)
    float* out = (float*)d_out;

    zero_kernel<<<1, 32>>>();
    gate_kernel<<<NTOK, 128>>>(h, gate_w);
    prefix_kernel<<<1, 32>>>();
    gemm1_mma<<<dim3(FDIM / 128, NTOK / 128, NEXP), 256>>>(h, w1, b1);
    gemm2_mma<<<dim3(DDIM / 128, NTOK / 128, NEXP), 256>>>(w2, b2);
    combine_kernel<<<(NTOK * DDIM) / 256, 256>>>(h, out);
}

// round 10
// speedup vs baseline: 1.9402x; 1.0461x over previous
#include <cuda_runtime.h>
#include <math.h>
#include <stdint.h>
#include <cuda_bf16.h>

#define NTOK 2048
#define DDIM 1024
#define NEXP 14
#define FDIM 2048
#define NPAIR (2*NTOK)
#define MPAD  (NPAIR + 128)

// ---------------- device scratch ---------------------------------------------
__device__ int   g_count[NEXP];
__device__ int   g_offset[NEXP];
__device__ int   g_pairs[NEXP][NTOK];      // value = token*2 + slot
__device__ float g_gatew[NTOK][2];
__device__ float g_h1[MPAD][FDIM];         // gemm1 output, row = offset[e]+m
__device__ float g_out2[NPAIR][DDIM];      // gemm2 output, row = pair id

// ---------------- helpers -------------------------------------------------------
__device__ __forceinline__ uint32_t to_tf32(float f) {
    uint32_t r;
    asm("cvt.rna.tf32.f32 %0, %1;" : "=r"(r) : "f"(f));
    return r;
}
__device__ __forceinline__ uint32_t smem_u32(const void* p) {
    uint32_t a;
    asm("{ .reg .u64 t; cvta.to.shared.u64 t, %1; cvt.u32.u64 %0, t; }" : "=r"(a) : "l"(p));
    return a;
}

#define MMA_TF32(d, a, b0, b1) \
    asm volatile("mma.sync.aligned.m16n8k8.row.col.f32.tf32.tf32.f32 " \
        "{%0,%1,%2,%3},{%4,%5,%6,%7},{%8,%9},{%0,%1,%2,%3};" \
        : "+f"((d)[0]), "+f"((d)[1]), "+f"((d)[2]), "+f"((d)[3]) \
        : "r"((a)[0]), "r"((a)[1]), "r"((a)[2]), "r"((a)[3]), "r"(b0), "r"(b1))

#define LDSM4(r, addr) \
    asm volatile("ldmatrix.sync.aligned.m8n8.x4.shared.b16 {%0,%1,%2,%3}, [%4];" \
        : "=r"((r)[0]), "=r"((r)[1]), "=r"((r)[2]), "=r"((r)[3]) : "r"(addr))

// ---------------- kernel: zero expert counts ----------------------------------
__global__ void zero_kernel() {
    if (threadIdx.x < NEXP) g_count[threadIdx.x] = 0;
}

// ---------------- kernel: gating (proven, fp32 exact) ---------------------------
__global__ void gate_kernel(const float* __restrict__ x,
                            const float* __restrict__ gw) {
    int n = blockIdx.x;
    __shared__ float sx[DDIM];
    __shared__ float red[128];
    __shared__ float logits[NEXP];
    const float* xr = x + (size_t)n * DDIM;
    for (int d = threadIdx.x; d < DDIM; d += 128) sx[d] = xr[d];
    __syncthreads();
    for (int e = 0; e < NEXP; e++) {
        const float* w = gw + (size_t)e * DDIM;
        float s = 0.f;
        for (int d = threadIdx.x; d < DDIM; d += 128) s += sx[d] * w[d];
        red[threadIdx.x] = s;
        __syncthreads();
        #pragma unroll
        for (int st = 64; st > 0; st >>= 1) {
            if (threadIdx.x < st) red[threadIdx.x] += red[threadIdx.x + st];
            __syncthreads();
        }
        if (threadIdx.x == 0) logits[e] = red[0];
        __syncthreads();
    }
    if (threadIdx.x == 0) {
        int i0 = 0; float l0 = logits[0];
        for (int e = 1; e < NEXP; e++) if (logits[e] > l0) { l0 = logits[e]; i0 = e; }
        int i1 = -1; float l1 = -3.0e38f;
        for (int e = 0; e < NEXP; e++) if (e != i0 && logits[e] > l1) { l1 = logits[e]; i1 = e; }
        float p1 = expf(l1 - l0);
        float inv = 1.0f / (1.0f + p1);
        g_gatew[n][0] = inv;
        g_gatew[n][1] = p1 * inv;
        int s0 = atomicAdd(&g_count[i0], 1);
        g_pairs[i0][s0] = n * 2 + 0;
        int s1 = atomicAdd(&g_count[i1], 1);
        g_pairs[i1][s1] = n * 2 + 1;
    }
}

__global__ void prefix_kernel() {
    if (threadIdx.x == 0) {
        int s = 0;
        for (int e = 0; e < NEXP; e++) { g_offset[e] = s; s += g_count[e]; }
    }
}

// =================================================================================
// TF32 GEMM mainloop layout:
//   S[0]=A, S[1]=B : each [128 rows][20 u32] (80-byte row stride, conflict-free
//   for both ldmatrix row-fetch and uint4 STS; 16 u32 payload = 16 k of tf32).
//   ldmatrix.x4 on b16 over a [8 rows x 4 fp32] tile delivers lane l element
//   (l/4, l%4) == the m16n8k8 tf32 fragment mapping. Same per-lane address
//   formulas as the proven bf16 kernel.
//   8 warps = 2(m) x 4(n); warp tile 64x32; single-pass tf32, fp32 accum.
// =================================================================================

// ---------------- GEMM1: h1 = gelu(x_gathered @ w1 + b1) -------------------------
__global__ void __launch_bounds__(256, 2)
gemm1_mma(const float* __restrict__ x,
          const float* __restrict__ w1,
          const float* __restrict__ b1) {
    int e = blockIdx.z, mt = blockIdx.y;
    int cnt = g_count[e];
    if (mt * 128 >= cnt) return;
    int nt = blockIdx.x;
    int off = g_offset[e];

    __shared__ uint32_t S[2][128][20];
    __shared__ int rowtok[128];

    int tid = threadIdx.x, lane = tid & 31, wid = tid >> 5;
    int wm = wid & 1, wn = wid >> 1;
    int g = lane >> 2, tig = lane & 3;

    if (tid < 128) {
        int m = mt * 128 + tid;
        rowtok[tid] = (m < cnt) ? (g_pairs[e][m] >> 1) : -1;
    }
    __syncthreads();

    int lm = tid & 127, kh = tid >> 7;
    int tok = rowtok[lm];
    const float* w1e = w1 + (size_t)e * DDIM * FDIM + nt * 128;
    const float* xrow = x + (size_t)(tok < 0 ? 0 : tok) * DDIM + kh * 8;
    const float* bcol = w1e + (size_t)kh * 8 * FDIM + lm;

    float fa[8], fb[8];
    auto ldg_chunk = [&](int c) {
        int k0 = c * 16;
        float4 u0 = make_float4(0.f, 0.f, 0.f, 0.f), u1 = u0;
        if (tok >= 0) {
            u0 = *(const float4*)(xrow + k0);
            u1 = *(const float4*)(xrow + k0 + 4);
        }
        fa[0] = u0.x; fa[1] = u0.y; fa[2] = u0.z; fa[3] = u0.w;
        fa[4] = u1.x; fa[5] = u1.y; fa[6] = u1.z; fa[7] = u1.w;
        const float* bp = bcol + (size_t)k0 * FDIM;
        #pragma unroll
        for (int j = 0; j < 8; j++) fb[j] = bp[(size_t)j * FDIM];
    };
    auto sts_chunk = [&]() {
        *(uint4*)&S[0][lm][kh * 8] =
            make_uint4(to_tf32(fa[0]), to_tf32(fa[1]), to_tf32(fa[2]), to_tf32(fa[3]));
        *(uint4*)&S[0][lm][kh * 8 + 4] =
            make_uint4(to_tf32(fa[4]), to_tf32(fa[5]), to_tf32(fa[6]), to_tf32(fa[7]));
        *(uint4*)&S[1][lm][kh * 8] =
            make_uint4(to_tf32(fb[0]), to_tf32(fb[1]), to_tf32(fb[2]), to_tf32(fb[3]));
        *(uint4*)&S[1][lm][kh * 8 + 4] =
            make_uint4(to_tf32(fb[4]), to_tf32(fb[5]), to_tf32(fb[6]), to_tf32(fb[7]));
    };

    // ldmatrix per-lane addresses (row stride 80B)
    uint32_t sbase = smem_u32(&S[0][0][0]);
    uint32_t aA = sbase + (wm * 64 + (lane & 15)) * 80 + (lane >> 4) * 16;
    uint32_t aB = sbase + 10240
                + (wn * 32 + ((lane >> 4) << 3) + (lane & 7)) * 80 + ((lane >> 3) & 1) * 16;

    float acc[4][4][4] = {};

    ldg_chunk(0);
    const int NCH = DDIM / 16;   // 64
    for (int c = 0; c < NCH; c++) {
        __syncthreads();
        sts_chunk();
        __syncthreads();
        if (c + 1 < NCH) ldg_chunk(c + 1);

        #pragma unroll
        for (int ks = 0; ks < 2; ks++) {
            uint32_t b01[4], b23[4];
            LDSM4(b01, aB + ks * 32);           // n-tiles 0,1: (b0,b1),(b0,b1)
            LDSM4(b23, aB + ks * 32 + 1280);    // n-tiles 2,3
            #pragma unroll
            for (int i = 0; i < 4; i++) {
                uint32_t a[4];
                LDSM4(a, aA + ks * 32 + i * 1280);
                MMA_TF32(acc[i][0], a, b01[0], b01[1]);
                MMA_TF32(acc[i][1], a, b01[2], b01[3]);
                MMA_TF32(acc[i][2], a, b23[0], b23[1]);
                MMA_TF32(acc[i][3], a, b23[2], b23[3]);
            }
        }
    }

    // epilogue: bias + exact gelu, fp32 store to g_h1
    int lim = cnt - mt * 128; if (lim > 128) lim = 128;
    const float* b1e = b1 + (size_t)e * FDIM + nt * 128;
    #pragma unroll
    for (int i = 0; i < 4; i++) {
        #pragma unroll
        for (int t = 0; t < 4; t++) {
            int col = wn * 32 + t * 8 + tig * 2;
            float bA = b1e[col], bB = b1e[col + 1];
            #pragma unroll
            for (int half = 0; half < 2; half++) {
                int r = wm * 64 + i * 16 + g + half * 8;
                if (r < lim) {
                    float v0 = acc[i][t][half * 2 + 0] + bA;
                    float v1 = acc[i][t][half * 2 + 1] + bB;
                    v0 = 0.5f * v0 * (1.0f + erff(v0 * 0.70710678118654752440f));
                    v1 = 0.5f * v1 * (1.0f + erff(v1 * 0.70710678118654752440f));
                    *(float2*)&g_h1[off + mt * 128 + r][nt * 128 + col] =
                        make_float2(v0, v1);
                }
            }
        }
    }
}

// ---------------- GEMM2: out2 = h1 @ w2 + b2, scatter by pair id -----------------
__global__ void __launch_bounds__(256, 2)
gemm2_mma(const float* __restrict__ w2,
          const float* __restrict__ b2) {
    int e = blockIdx.z, mt = blockIdx.y;
    int cnt = g_count[e];
    if (mt * 128 >= cnt) return;
    int nt = blockIdx.x;
    int off = g_offset[e];
    int mrow0 = off + mt * 128;

    __shared__ uint32_t S[2][128][20];
    __shared__ int pid[128];

    int tid = threadIdx.x, lane = tid & 31, wid = tid >> 5;
    int wm = wid & 1, wn = wid >> 1;
    int g = lane >> 2, tig = lane & 3;

    if (tid < 128) {
        int m = mt * 128 + tid;
        pid[tid] = (m < cnt) ? g_pairs[e][m] : 0;
    }
    __syncthreads();

    int lm = tid & 127, kh = tid >> 7;
    const float* w2e = w2 + (size_t)e * FDIM * DDIM + nt * 128;
    const float* arow = &g_h1[mrow0 + lm][kh * 8];
    const float* bcol = w2e + (size_t)kh * 8 * DDIM + lm;

    float fa[8], fb[8];
    auto ldg_chunk = [&](int c) {
        int k0 = c * 16;
        float4 u0 = *(const float4*)(arow + k0);
        float4 u1 = *(const float4*)(arow + k0 + 4);
        fa[0] = u0.x; fa[1] = u0.y; fa[2] = u0.z; fa[3] = u0.w;
        fa[4] = u1.x; fa[5] = u1.y; fa[6] = u1.z; fa[7] = u1.w;
        const float* bp = bcol + (size_t)k0 * DDIM;
        #pragma unroll
        for (int j = 0; j < 8; j++) fb[j] = bp[(size_t)j * DDIM];
    };
    auto sts_chunk = [&]() {
        *(uint4*)&S[0][lm][kh * 8] =
            make_uint4(to_tf32(fa[0]), to_tf32(fa[1]), to_tf32(fa[2]), to_tf32(fa[3]));
        *(uint4*)&S[0][lm][kh * 8 + 4] =
            make_uint4(to_tf32(fa[4]), to_tf32(fa[5]), to_tf32(fa[6]), to_tf32(fa[7]));
        *(uint4*)&S[1][lm][kh * 8] =
            make_uint4(to_tf32(fb[0]), to_tf32(fb[1]), to_tf32(fb[2]), to_tf32(fb[3]));
        *(uint4*)&S[1][lm][kh * 8 + 4] =
            make_uint4(to_tf32(fb[4]), to_tf32(fb[5]), to_tf32(fb[6]), to_tf32(fb[7]));
    };

    uint32_t sbase = smem_u32(&S[0][0][0]);
    uint32_t aA = sbase + (wm * 64 + (lane & 15)) * 80 + (lane >> 4) * 16;
    uint32_t aB = sbase + 10240
                + (wn * 32 + ((lane >> 4) << 3) + (lane & 7)) * 80 + ((lane >> 3) & 1) * 16;

    float acc[4][4][4] = {};

    ldg_chunk(0);
    const int NCH = FDIM / 16;   // 128
    for (int c = 0; c < NCH; c++) {
        __syncthreads();
        sts_chunk();
        __syncthreads();
        if (c + 1 < NCH) ldg_chunk(c + 1);

        #pragma unroll
        for (int ks = 0; ks < 2; ks++) {
            uint32_t b01[4], b23[4];
            LDSM4(b01, aB + ks * 32);
            LDSM4(b23, aB + ks * 32 + 1280);
            #pragma unroll
            for (int i = 0; i < 4; i++) {
                uint32_t a[4];
                LDSM4(a, aA + ks * 32 + i * 1280);
                MMA_TF32(acc[i][0], a, b01[0], b01[1]);
                MMA_TF32(acc[i][1], a, b01[2], b01[3]);
                MMA_TF32(acc[i][2], a, b23[0], b23[1]);
                MMA_TF32(acc[i][3], a, b23[2], b23[3]);
            }
        }
    }

    // epilogue: bias, scatter rows by pair id
    int lim = cnt - mt * 128; if (lim > 128) lim = 128;
    const float* b2e = b2 + (size_t)e * DDIM + nt * 128;
    #pragma unroll
    for (int i = 0; i < 4; i++) {
        #pragma unroll
        for (int t = 0; t < 4; t++) {
            int col = wn * 32 + t * 8 + tig * 2;
            float bA = b2e[col], bB = b2e[col + 1];
            #pragma unroll
            for (int half = 0; half < 2; half++) {
                int r = wm * 64 + i * 16 + g + half * 8;
                if (r < lim) {
                    int pr = pid[r];
                    *(float2*)&g_out2[pr][nt * 128 + col] =
                        make_float2(acc[i][t][half * 2 + 0] + bA,
                                    acc[i][t][half * 2 + 1] + bB);
                }
            }
        }
    }
}

// ---------------- combine: out = clip(x + w0*o0 + w1*o1, +-100) -----------------
__global__ void combine_kernel(const float* __restrict__ x,
                               float* __restrict__ out) {
    int i = blockIdx.x * 256 + threadIdx.x;
    int n = i >> 10;
    int d = i & 1023;
    float v = x[i]
            + g_gatew[n][0] * g_out2[2 * n + 0][d]
            + g_gatew[n][1] * g_out2[2 * n + 1][d];
    out[i] = fminf(fmaxf(v, -100.0f), 100.0f);
}

// ---------------- launch --------------------------------------------------------
extern "C" void kernel_launch(void* const* d_in, const int* in_sizes, int n_in,
                              void* d_out, int out_size) {
    const float* h      = (const float*)d_in[0];   // (2,1024,1024)
    const float* gate_w = (const float*)d_in[1];   // (14,1024)
    const float* w1     = (const float*)d_in[2];   // (14,1024,2048)
    const float* b1     = (const float*)d_in[3];   // (14,2048)
    const float* w2     = (const float*)d_in[4];   // (14,2048,1024)
    const float* b2     = (const float*)d_in[5];   // (14,1024)
    float* out = (float*)d_out;

    zero_kernel<<<1, 32>>>();
    gate_kernel<<<NTOK, 128>>>(h, gate_w);
    prefix_kernel<<<1, 32>>>();
    gemm1_mma<<<dim3(FDIM / 128, NTOK / 128, NEXP), 256>>>(h, w1, b1);
    gemm2_mma<<<dim3(DDIM / 128, NTOK / 128, NEXP), 256>>>(w2, b2);
    combine_kernel<<<(NTOK * DDIM) / 256, 256>>>(h, out);
}

// round 11
// speedup vs baseline: 2.3355x; 1.2037x over previous
#include <cuda_runtime.h>
#include <math.h>
#include <stdint.h>
#include <cuda_bf16.h>

#define NTOK 2048
#define DDIM 1024
#define NEXP 14
#define FDIM 2048
#define NPAIR (2*NTOK)
#define MPAD  (NPAIR + 128)

// ---------------- device scratch ---------------------------------------------
__device__ int   g_count[NEXP];
__device__ int   g_offset[NEXP];
__device__ int   g_pairs[NEXP][NTOK];      // value = token*2 + slot
__device__ float g_gatew[NTOK][2];
__device__ float g_h1[MPAD][FDIM];         // gemm1 output, row = offset[e]+m
__device__ float g_out2[NPAIR][DDIM];      // gemm2 output, row = pair id

// ---------------- helpers -------------------------------------------------------
__device__ __forceinline__ uint32_t smem_u32(const void* p) {
    uint32_t a;
    asm("{ .reg .u64 t; cvta.to.shared.u64 t, %1; cvt.u32.u64 %0, t; }" : "=r"(a) : "l"(p));
    return a;
}

#define MMA_TF32(d, a, b0, b1) \
    asm volatile("mma.sync.aligned.m16n8k8.row.col.f32.tf32.tf32.f32 " \
        "{%0,%1,%2,%3},{%4,%5,%6,%7},{%8,%9},{%0,%1,%2,%3};" \
        : "+f"((d)[0]), "+f"((d)[1]), "+f"((d)[2]), "+f"((d)[3]) \
        : "r"((a)[0]), "r"((a)[1]), "r"((a)[2]), "r"((a)[3]), "r"(b0), "r"(b1))

#define LDSM4(r, addr) \
    asm volatile("ldmatrix.sync.aligned.m8n8.x4.shared.b16 {%0,%1,%2,%3}, [%4];" \
        : "=r"((r)[0]), "=r"((r)[1]), "=r"((r)[2]), "=r"((r)[3]) : "r"(addr))

// ---------------- kernel: zero expert counts ----------------------------------
__global__ void zero_kernel() {
    if (threadIdx.x < NEXP) g_count[threadIdx.x] = 0;
}

// ---------------- kernel: gating — warp per token, shuffle reductions ----------
__global__ void gate_kernel(const float* __restrict__ x,
                            const float* __restrict__ gw) {
    int lane = threadIdx.x & 31, wid = threadIdx.x >> 5;
    int n = blockIdx.x * 8 + wid;
    const float4* xr = (const float4*)(x + (size_t)n * DDIM);
    float4 xv[8];
    #pragma unroll
    for (int i = 0; i < 8; i++) xv[i] = xr[i * 32 + lane];

    float l0 = -3.0e38f, l1 = -3.0e38f;
    int i0 = 0, i1 = -1;
    for (int e = 0; e < NEXP; e++) {
        const float4* we = (const float4*)(gw + (size_t)e * DDIM);
        float s = 0.f;
        #pragma unroll
        for (int i = 0; i < 8; i++) {
            float4 b = we[i * 32 + lane];
            s += xv[i].x * b.x + xv[i].y * b.y + xv[i].z * b.z + xv[i].w * b.w;
        }
        #pragma unroll
        for (int o = 16; o; o >>= 1) s += __shfl_xor_sync(0xFFFFFFFFu, s, o);
        if (s > l0)      { l1 = l0; i1 = i0; l0 = s; i0 = e; }
        else if (s > l1) { l1 = s;  i1 = e; }
    }
    if (lane == 0) {
        float p1 = expf(l1 - l0);
        float inv = 1.0f / (1.0f + p1);
        g_gatew[n][0] = inv;
        g_gatew[n][1] = p1 * inv;
        int s0 = atomicAdd(&g_count[i0], 1);
        g_pairs[i0][s0] = n * 2 + 0;
        int s1 = atomicAdd(&g_count[i1], 1);
        g_pairs[i1][s1] = n * 2 + 1;
    }
}

__global__ void prefix_kernel() {
    if (threadIdx.x == 0) {
        int s = 0;
        for (int e = 0; e < NEXP; e++) { g_offset[e] = s; s += g_count[e]; }
    }
}

// =================================================================================
// TF32 GEMM (truncated fp32 bits fed directly to tensor core):
//   SA: [128 m][20 u32]  (80B stride) — A rows, frags via ldmatrix.x4 (proven).
//   SB: [16 k][136 u32]  (544B stride) — B in gmem layout; loader 2xLDG.128 +
//       2xSTS.128 (conflict-free: 4l banks); frags via scalar LDS.32, bank walk
//       (l&3)*8 + (l>>2) = 32 distinct banks (conflict-free).
//   8 warps = 2(m) x 4(n); warp tile 64x32; m16n8k8 tf32, fp32 accum.
// =================================================================================

// ---------------- GEMM1: h1 = gelu(x_gathered @ w1 + b1) -------------------------
__global__ void __launch_bounds__(256, 2)
gemm1_mma(const float* __restrict__ x,
          const float* __restrict__ w1,
          const float* __restrict__ b1) {
    int e = blockIdx.z, mt = blockIdx.y;
    int cnt = g_count[e];
    if (mt * 128 >= cnt) return;
    int nt = blockIdx.x;
    int off = g_offset[e];

    __shared__ uint32_t SA[128][20];
    __shared__ uint32_t SB[16][136];
    __shared__ int rowtok[128];

    int tid = threadIdx.x, lane = tid & 31, wid = tid >> 5;
    int wm = wid & 1, wn = wid >> 1;
    int g = lane >> 2, tig = lane & 3;

    if (tid < 128) {
        int m = mt * 128 + tid;
        rowtok[tid] = (m < cnt) ? (g_pairs[e][m] >> 1) : -1;
    }
    __syncthreads();

    // A loader: lm = row, kh = k-half (8 floats each)
    int lm = tid & 127, kh = tid >> 7;
    int tok = rowtok[lm];
    const float* xrow = x + (size_t)(tok < 0 ? 0 : tok) * DDIM + kh * 8;
    // B loader: bk = k-row (2 passes of 8), bn = 4-float col group
    int bk = tid >> 5, bn = (tid & 31) * 4;
    const float* w1e = w1 + (size_t)e * DDIM * FDIM + nt * 128;
    const float* bsrc = w1e + (size_t)bk * FDIM + bn;

    uint4 ra0, ra1, rb0, rb1;
    auto ldg_chunk = [&](int c) {
        int k0 = c * 16;
        if (tok >= 0) {
            ra0 = *(const uint4*)(xrow + k0);
            ra1 = *(const uint4*)(xrow + k0 + 4);
        } else {
            ra0 = make_uint4(0, 0, 0, 0); ra1 = ra0;
        }
        rb0 = *(const uint4*)(bsrc + (size_t)k0 * FDIM);
        rb1 = *(const uint4*)(bsrc + (size_t)(k0 + 8) * FDIM);
    };
    auto sts_chunk = [&]() {
        *(uint4*)&SA[lm][kh * 8]     = ra0;
        *(uint4*)&SA[lm][kh * 8 + 4] = ra1;
        *(uint4*)&SB[bk][bn]     = rb0;
        *(uint4*)&SB[bk + 8][bn] = rb1;
    };

    // fragment addressing
    uint32_t aA = smem_u32(&SA[0][0]) + (wm * 64 + (lane & 15)) * 80 + (lane >> 4) * 16;
    int bn0 = wn * 32 + (lane >> 2);   // + t*8
    int bk0 = lane & 3;                // + ks*8 (+4 for second reg)

    float acc[4][4][4] = {};

    ldg_chunk(0);
    const int NCH = DDIM / 16;   // 64
    for (int c = 0; c < NCH; c++) {
        __syncthreads();
        sts_chunk();
        __syncthreads();
        if (c + 1 < NCH) ldg_chunk(c + 1);

        // preload all B fragments: 4 t x 2 ks x 2 regs
        uint32_t bf[4][2][2];
        #pragma unroll
        for (int t = 0; t < 4; t++)
            #pragma unroll
            for (int ks = 0; ks < 2; ks++) {
                bf[t][ks][0] = SB[ks * 8 + bk0][bn0 + t * 8];
                bf[t][ks][1] = SB[ks * 8 + bk0 + 4][bn0 + t * 8];
            }
        #pragma unroll
        for (int ks = 0; ks < 2; ks++)
            #pragma unroll
            for (int i = 0; i < 4; i++) {
                uint32_t a[4];
                LDSM4(a, aA + ks * 32 + i * 1280);
                MMA_TF32(acc[i][0], a, bf[0][ks][0], bf[0][ks][1]);
                MMA_TF32(acc[i][1], a, bf[1][ks][0], bf[1][ks][1]);
                MMA_TF32(acc[i][2], a, bf[2][ks][0], bf[2][ks][1]);
                MMA_TF32(acc[i][3], a, bf[3][ks][0], bf[3][ks][1]);
            }
    }

    // epilogue: bias + exact gelu, fp32 store to g_h1
    int lim = cnt - mt * 128; if (lim > 128) lim = 128;
    const float* b1e = b1 + (size_t)e * FDIM + nt * 128;
    #pragma unroll
    for (int i = 0; i < 4; i++) {
        #pragma unroll
        for (int t = 0; t < 4; t++) {
            int col = wn * 32 + t * 8 + tig * 2;
            float bA = b1e[col], bB = b1e[col + 1];
            #pragma unroll
            for (int half = 0; half < 2; half++) {
                int r = wm * 64 + i * 16 + g + half * 8;
                if (r < lim) {
                    float v0 = acc[i][t][half * 2 + 0] + bA;
                    float v1 = acc[i][t][half * 2 + 1] + bB;
                    v0 = 0.5f * v0 * (1.0f + erff(v0 * 0.70710678118654752440f));
                    v1 = 0.5f * v1 * (1.0f + erff(v1 * 0.70710678118654752440f));
                    *(float2*)&g_h1[off + mt * 128 + r][nt * 128 + col] =
                        make_float2(v0, v1);
                }
            }
        }
    }
}

// ---------------- GEMM2: out2 = h1 @ w2 + b2, scatter by pair id -----------------
__global__ void __launch_bounds__(256, 2)
gemm2_mma(const float* __restrict__ w2,
          const float* __restrict__ b2) {
    int e = blockIdx.z, mt = blockIdx.y;
    int cnt = g_count[e];
    if (mt * 128 >= cnt) return;
    int nt = blockIdx.x;
    int off = g_offset[e];
    int mrow0 = off + mt * 128;

    __shared__ uint32_t SA[128][20];
    __shared__ uint32_t SB[16][136];
    __shared__ int pid[128];

    int tid = threadIdx.x, lane = tid & 31, wid = tid >> 5;
    int wm = wid & 1, wn = wid >> 1;
    int g = lane >> 2, tig = lane & 3;

    if (tid < 128) {
        int m = mt * 128 + tid;
        pid[tid] = (m < cnt) ? g_pairs[e][m] : 0;
    }
    __syncthreads();

    int lm = tid & 127, kh = tid >> 7;
    const float* arow = &g_h1[mrow0 + lm][kh * 8];
    int bk = tid >> 5, bn = (tid & 31) * 4;
    const float* w2e = w2 + (size_t)e * FDIM * DDIM + nt * 128;
    const float* bsrc = w2e + (size_t)bk * DDIM + bn;

    uint4 ra0, ra1, rb0, rb1;
    auto ldg_chunk = [&](int c) {
        int k0 = c * 16;
        ra0 = *(const uint4*)(arow + k0);
        ra1 = *(const uint4*)(arow + k0 + 4);
        rb0 = *(const uint4*)(bsrc + (size_t)k0 * DDIM);
        rb1 = *(const uint4*)(bsrc + (size_t)(k0 + 8) * DDIM);
    };
    auto sts_chunk = [&]() {
        *(uint4*)&SA[lm][kh * 8]     = ra0;
        *(uint4*)&SA[lm][kh * 8 + 4] = ra1;
        *(uint4*)&SB[bk][bn]     = rb0;
        *(uint4*)&SB[bk + 8][bn] = rb1;
    };

    uint32_t aA = smem_u32(&SA[0][0]) + (wm * 64 + (lane & 15)) * 80 + (lane >> 4) * 16;
    int bn0 = wn * 32 + (lane >> 2);
    int bk0 = lane & 3;

    float acc[4][4][4] = {};

    ldg_chunk(0);
    const int NCH = FDIM / 16;   // 128
    for (int c = 0; c < NCH; c++) {
        __syncthreads();
        sts_chunk();
        __syncthreads();
        if (c + 1 < NCH) ldg_chunk(c + 1);

        uint32_t bf[4][2][2];
        #pragma unroll
        for (int t = 0; t < 4; t++)
            #pragma unroll
            for (int ks = 0; ks < 2; ks++) {
                bf[t][ks][0] = SB[ks * 8 + bk0][bn0 + t * 8];
                bf[t][ks][1] = SB[ks * 8 + bk0 + 4][bn0 + t * 8];
            }
        #pragma unroll
        for (int ks = 0; ks < 2; ks++)
            #pragma unroll
            for (int i = 0; i < 4; i++) {
                uint32_t a[4];
                LDSM4(a, aA + ks * 32 + i * 1280);
                MMA_TF32(acc[i][0], a, bf[0][ks][0], bf[0][ks][1]);
                MMA_TF32(acc[i][1], a, bf[1][ks][0], bf[1][ks][1]);
                MMA_TF32(acc[i][2], a, bf[2][ks][0], bf[2][ks][1]);
                MMA_TF32(acc[i][3], a, bf[3][ks][0], bf[3][ks][1]);
            }
    }

    // epilogue: bias, scatter rows by pair id
    int lim = cnt - mt * 128; if (lim > 128) lim = 128;
    const float* b2e = b2 + (size_t)e * DDIM + nt * 128;
    #pragma unroll
    for (int i = 0; i < 4; i++) {
        #pragma unroll
        for (int t = 0; t < 4; t++) {
            int col = wn * 32 + t * 8 + tig * 2;
            float bA = b2e[col], bB = b2e[col + 1];
            #pragma unroll
            for (int half = 0; half < 2; half++) {
                int r = wm * 64 + i * 16 + g + half * 8;
                if (r < lim) {
                    int pr = pid[r];
                    *(float2*)&g_out2[pr][nt * 128 + col] =
                        make_float2(acc[i][t][half * 2 + 0] + bA,
                                    acc[i][t][half * 2 + 1] + bB);
                }
            }
        }
    }
}

// ---------------- combine: out = clip(x + w0*o0 + w1*o1, +-100) -----------------
__global__ void combine_kernel(const float* __restrict__ x,
                               float* __restrict__ out) {
    int i = blockIdx.x * 256 + threadIdx.x;
    int n = i >> 10;
    int d = i & 1023;
    float v = x[i]
            + g_gatew[n][0] * g_out2[2 * n + 0][d]
            + g_gatew[n][1] * g_out2[2 * n + 1][d];
    out[i] = fminf(fmaxf(v, -100.0f), 100.0f);
}

// ---------------- launch --------------------------------------------------------
extern "C" void kernel_launch(void* const* d_in, const int* in_sizes, int n_in,
                              void* d_out, int out_size) {
    const float* h      = (const float*)d_in[0];   // (2,1024,1024)
    const float* gate_w = (const float*)d_in[1];   // (14,1024)
    const float* w1     = (const float*)d_in[2];   // (14,1024,2048)
    const float* b1     = (const float*)d_in[3];   // (14,2048)
    const float* w2     = (const float*)d_in[4];   // (14,2048,1024)
    const float* b2     = (const float*)d_in[5];   // (14,1024)
    float* out = (float*)d_out;

    zero_kernel<<<1, 32>>>();
    gate_kernel<<<NTOK / 8, 256>>>(h, gate_w);
    prefix_kernel<<<1, 32>>>();
    gemm1_mma<<<dim3(FDIM / 128, NTOK / 128, NEXP), 256>>>(h, w1, b1);
    gemm2_mma<<<dim3(DDIM / 128, NTOK / 128, NEXP), 256>>>(w2, b2);
    combine_kernel<<<(NTOK * DDIM) / 256, 256>>>(h, out);
}

// round 12
// speedup vs baseline: 2.5460x; 1.0901x over previous
#include <cuda_runtime.h>
#include <math.h>
#include <stdint.h>
#include <cuda_bf16.h>

#define NTOK 2048
#define DDIM 1024
#define NEXP 14
#define FDIM 2048
#define NPAIR (2*NTOK)
#define MPAD  (NPAIR + 128)

// ---------------- device scratch ---------------------------------------------
__device__ int   g_count[NEXP];
__device__ int   g_offset[NEXP];
__device__ int   g_pairs[NEXP][NTOK];      // value = token*2 + slot
__device__ float g_gatew[NTOK][2];
__device__ float g_h1[MPAD][FDIM];         // gemm1 output, row = offset[e]+m
__device__ float g_out2[NPAIR][DDIM];      // gemm2 partial (k-split 0, + bias)
__device__ float g_out2b[NPAIR][DDIM];     // gemm2 partial (k-split 1)

// ---------------- helpers -------------------------------------------------------
__device__ __forceinline__ uint32_t to_tf32(float f) {
    uint32_t r;
    asm("cvt.rna.tf32.f32 %0, %1;" : "=r"(r) : "f"(f));
    return r;
}
__device__ __forceinline__ uint32_t smem_u32(const void* p) {
    uint32_t a;
    asm("{ .reg .u64 t; cvta.to.shared.u64 t, %1; cvt.u32.u64 %0, t; }" : "=r"(a) : "l"(p));
    return a;
}

#define MMA_TF32(d, a, b0, b1) \
    asm volatile("mma.sync.aligned.m16n8k8.row.col.f32.tf32.tf32.f32 " \
        "{%0,%1,%2,%3},{%4,%5,%6,%7},{%8,%9},{%0,%1,%2,%3};" \
        : "+f"((d)[0]), "+f"((d)[1]), "+f"((d)[2]), "+f"((d)[3]) \
        : "r"((a)[0]), "r"((a)[1]), "r"((a)[2]), "r"((a)[3]), "r"(b0), "r"(b1))

#define LDSM4(r, addr) \
    asm volatile("ldmatrix.sync.aligned.m8n8.x4.shared.b16 {%0,%1,%2,%3}, [%4];" \
        : "=r"((r)[0]), "=r"((r)[1]), "=r"((r)[2]), "=r"((r)[3]) : "r"(addr))

// ---------------- kernel: zero expert counts ----------------------------------
__global__ void zero_kernel() {
    if (threadIdx.x < NEXP) g_count[threadIdx.x] = 0;
}

// ---------------- kernel: gating — warp per token, shuffle reductions ----------
__global__ void gate_kernel(const float* __restrict__ x,
                            const float* __restrict__ gw) {
    int lane = threadIdx.x & 31, wid = threadIdx.x >> 5;
    int n = blockIdx.x * 8 + wid;
    const float4* xr = (const float4*)(x + (size_t)n * DDIM);
    float4 xv[8];
    #pragma unroll
    for (int i = 0; i < 8; i++) xv[i] = xr[i * 32 + lane];

    float l0 = -3.0e38f, l1 = -3.0e38f;
    int i0 = 0, i1 = -1;
    for (int e = 0; e < NEXP; e++) {
        const float4* we = (const float4*)(gw + (size_t)e * DDIM);
        float s = 0.f;
        #pragma unroll
        for (int i = 0; i < 8; i++) {
            float4 b = we[i * 32 + lane];
            s += xv[i].x * b.x + xv[i].y * b.y + xv[i].z * b.z + xv[i].w * b.w;
        }
        #pragma unroll
        for (int o = 16; o; o >>= 1) s += __shfl_xor_sync(0xFFFFFFFFu, s, o);
        if (s > l0)      { l1 = l0; i1 = i0; l0 = s; i0 = e; }
        else if (s > l1) { l1 = s;  i1 = e; }
    }
    if (lane == 0) {
        float p1 = expf(l1 - l0);
        float inv = 1.0f / (1.0f + p1);
        g_gatew[n][0] = inv;
        g_gatew[n][1] = p1 * inv;
        int s0 = atomicAdd(&g_count[i0], 1);
        g_pairs[i0][s0] = n * 2 + 0;
        int s1 = atomicAdd(&g_count[i1], 1);
        g_pairs[i1][s1] = n * 2 + 1;
    }
}

__global__ void prefix_kernel() {
    if (threadIdx.x == 0) {
        int s = 0;
        for (int e = 0; e < NEXP; e++) { g_offset[e] = s; s += g_count[e]; }
    }
}

// =================================================================================
// TF32 GEMM (cvt.rna operands), DOUBLE-BUFFERED single-sync mainloop:
//   SA[2]: [128 m][20 u32]  (80B stride) — A rows, frags via ldmatrix.x4.
//   SB[2]: [16 k][136 u32]  (544B stride) — B gmem layout; frags via scalar LDS.
//   8 warps = 2(m) x 4(n); warp tile 64x32; m16n8k8 tf32, fp32 accum.
//   Pair-unrolled: even chunk -> buf0, odd -> buf1; one __syncthreads per chunk.
// =================================================================================
#define SA_BUFB 10240   // 128*20*4

// ---------------- GEMM1: h1 = gelu(x_gathered @ w1 + b1) -------------------------
__global__ void __launch_bounds__(256, 2)
gemm1_mma(const float* __restrict__ x,
          const float* __restrict__ w1,
          const float* __restrict__ b1) {
    int e = blockIdx.z, mt = blockIdx.y;
    int cnt = g_count[e];
    if (mt * 128 >= cnt) return;
    int nt = blockIdx.x;
    int off = g_offset[e];

    __shared__ uint32_t SA[2][128][20];
    __shared__ uint32_t SB[2][16][136];
    __shared__ int rowtok[128];

    int tid = threadIdx.x, lane = tid & 31, wid = tid >> 5;
    int wm = wid & 1, wn = wid >> 1;
    int g = lane >> 2, tig = lane & 3;

    if (tid < 128) {
        int m = mt * 128 + tid;
        rowtok[tid] = (m < cnt) ? (g_pairs[e][m] >> 1) : -1;
    }
    __syncthreads();

    int lm = tid & 127, kh = tid >> 7;
    int tok = rowtok[lm];
    const float* xrow = x + (size_t)(tok < 0 ? 0 : tok) * DDIM + kh * 8;
    int bk = tid >> 5, bn = (tid & 31) * 4;
    const float* w1e = w1 + (size_t)e * DDIM * FDIM + nt * 128;
    const float* bsrc = w1e + (size_t)bk * FDIM + bn;

    float4 ra0, ra1, rb0, rb1;
    auto ldg_chunk = [&](int c) {
        int k0 = c * 16;
        if (tok >= 0) {
            ra0 = *(const float4*)(xrow + k0);
            ra1 = *(const float4*)(xrow + k0 + 4);
        } else {
            ra0 = make_float4(0.f, 0.f, 0.f, 0.f); ra1 = ra0;
        }
        rb0 = *(const float4*)(bsrc + (size_t)k0 * FDIM);
        rb1 = *(const float4*)(bsrc + (size_t)(k0 + 8) * FDIM);
    };
    auto sts_chunk = [&](int buf) {
        *(uint4*)&SA[buf][lm][kh * 8] =
            make_uint4(to_tf32(ra0.x), to_tf32(ra0.y), to_tf32(ra0.z), to_tf32(ra0.w));
        *(uint4*)&SA[buf][lm][kh * 8 + 4] =
            make_uint4(to_tf32(ra1.x), to_tf32(ra1.y), to_tf32(ra1.z), to_tf32(ra1.w));
        *(uint4*)&SB[buf][bk][bn] =
            make_uint4(to_tf32(rb0.x), to_tf32(rb0.y), to_tf32(rb0.z), to_tf32(rb0.w));
        *(uint4*)&SB[buf][bk + 8][bn] =
            make_uint4(to_tf32(rb1.x), to_tf32(rb1.y), to_tf32(rb1.z), to_tf32(rb1.w));
    };

    uint32_t aA0 = smem_u32(&SA[0][0][0]) + (wm * 64 + (lane & 15)) * 80 + (lane >> 4) * 16;
    int bn0 = wn * 32 + (lane >> 2);
    int bk0 = lane & 3;

    float acc[4][4][4] = {};

    auto compute = [&](uint32_t aAb, const uint32_t (&sB)[16][136]) {
        uint32_t bf[4][2][2];
        #pragma unroll
        for (int t = 0; t < 4; t++)
            #pragma unroll
            for (int ks = 0; ks < 2; ks++) {
                bf[t][ks][0] = sB[ks * 8 + bk0][bn0 + t * 8];
                bf[t][ks][1] = sB[ks * 8 + bk0 + 4][bn0 + t * 8];
            }
        #pragma unroll
        for (int ks = 0; ks < 2; ks++)
            #pragma unroll
            for (int i = 0; i < 4; i++) {
                uint32_t a[4];
                LDSM4(a, aAb + ks * 32 + i * 1280);
                MMA_TF32(acc[i][0], a, bf[0][ks][0], bf[0][ks][1]);
                MMA_TF32(acc[i][1], a, bf[1][ks][0], bf[1][ks][1]);
                MMA_TF32(acc[i][2], a, bf[2][ks][0], bf[2][ks][1]);
                MMA_TF32(acc[i][3], a, bf[3][ks][0], bf[3][ks][1]);
            }
    };

    const int NCH = DDIM / 16;   // 64 (even)
    ldg_chunk(0);
    sts_chunk(0);
    __syncthreads();
    for (int c = 0; c < NCH; c += 2) {
        ldg_chunk(c + 1);
        compute(aA0, SB[0]);
        sts_chunk(1);
        __syncthreads();
        if (c + 2 < NCH) ldg_chunk(c + 2);
        compute(aA0 + SA_BUFB, SB[1]);
        if (c + 2 < NCH) sts_chunk(0);
        __syncthreads();
    }

    // epilogue: bias + exact gelu, fp32 store to g_h1
    int lim = cnt - mt * 128; if (lim > 128) lim = 128;
    const float* b1e = b1 + (size_t)e * FDIM + nt * 128;
    #pragma unroll
    for (int i = 0; i < 4; i++) {
        #pragma unroll
        for (int t = 0; t < 4; t++) {
            int col = wn * 32 + t * 8 + tig * 2;
            float bA = b1e[col], bB = b1e[col + 1];
            #pragma unroll
            for (int half = 0; half < 2; half++) {
                int r = wm * 64 + i * 16 + g + half * 8;
                if (r < lim) {
                    float v0 = acc[i][t][half * 2 + 0] + bA;
                    float v1 = acc[i][t][half * 2 + 1] + bB;
                    v0 = 0.5f * v0 * (1.0f + erff(v0 * 0.70710678118654752440f));
                    v1 = 0.5f * v1 * (1.0f + erff(v1 * 0.70710678118654752440f));
                    *(float2*)&g_h1[off + mt * 128 + r][nt * 128 + col] =
                        make_float2(v0, v1);
                }
            }
        }
    }
}

// ---------------- GEMM2 (split-K x2): out2[s] = h1[:, sK:] @ w2[sK:, :] ----------
__global__ void __launch_bounds__(256, 2)
gemm2_mma(const float* __restrict__ w2,
          const float* __restrict__ b2) {
    int ez = blockIdx.z;
    int e = ez >> 1, sp = ez & 1;
    int mt = blockIdx.y;
    int cnt = g_count[e];
    if (mt * 128 >= cnt) return;
    int nt = blockIdx.x;
    int off = g_offset[e];
    int mrow0 = off + mt * 128;

    __shared__ uint32_t SA[2][128][20];
    __shared__ uint32_t SB[2][16][136];
    __shared__ int pid[128];

    int tid = threadIdx.x, lane = tid & 31, wid = tid >> 5;
    int wm = wid & 1, wn = wid >> 1;
    int g = lane >> 2, tig = lane & 3;

    if (tid < 128) {
        int m = mt * 128 + tid;
        pid[tid] = (m < cnt) ? g_pairs[e][m] : 0;
    }
    __syncthreads();

    int lm = tid & 127, kh = tid >> 7;
    const float* arow = &g_h1[mrow0 + lm][sp * 1024 + kh * 8];
    int bk = tid >> 5, bn = (tid & 31) * 4;
    const float* w2e = w2 + (size_t)e * FDIM * DDIM + nt * 128;
    const float* bsrc = w2e + (size_t)(sp * 1024 + bk) * DDIM + bn;

    float4 ra0, ra1, rb0, rb1;
    auto ldg_chunk = [&](int c) {
        int k0 = c * 16;
        ra0 = *(const float4*)(arow + k0);
        ra1 = *(const float4*)(arow + k0 + 4);
        rb0 = *(const float4*)(bsrc + (size_t)k0 * DDIM);
        rb1 = *(const float4*)(bsrc + (size_t)(k0 + 8) * DDIM);
    };
    auto sts_chunk = [&](int buf) {
        *(uint4*)&SA[buf][lm][kh * 8] =
            make_uint4(to_tf32(ra0.x), to_tf32(ra0.y), to_tf32(ra0.z), to_tf32(ra0.w));
        *(uint4*)&SA[buf][lm][kh * 8 + 4] =
            make_uint4(to_tf32(ra1.x), to_tf32(ra1.y), to_tf32(ra1.z), to_tf32(ra1.w));
        *(uint4*)&SB[buf][bk][bn] =
            make_uint4(to_tf32(rb0.x), to_tf32(rb0.y), to_tf32(rb0.z), to_tf32(rb0.w));
        *(uint4*)&SB[buf][bk + 8][bn] =
            make_uint4(to_tf32(rb1.x), to_tf32(rb1.y), to_tf32(rb1.z), to_tf32(rb1.w));
    };

    uint32_t aA0 = smem_u32(&SA[0][0][0]) + (wm * 64 + (lane & 15)) * 80 + (lane >> 4) * 16;
    int bn0 = wn * 32 + (lane >> 2);
    int bk0 = lane & 3;

    float acc[4][4][4] = {};

    auto compute = [&](uint32_t aAb, const uint32_t (&sB)[16][136]) {
        uint32_t bf[4][2][2];
        #pragma unroll
        for (int t = 0; t < 4; t++)
            #pragma unroll
            for (int ks = 0; ks < 2; ks++) {
                bf[t][ks][0] = sB[ks * 8 + bk0][bn0 + t * 8];
                bf[t][ks][1] = sB[ks * 8 + bk0 + 4][bn0 + t * 8];
            }
        #pragma unroll
        for (int ks = 0; ks < 2; ks++)
            #pragma unroll
            for (int i = 0; i < 4; i++) {
                uint32_t a[4];
                LDSM4(a, aAb + ks * 32 + i * 1280);
                MMA_TF32(acc[i][0], a, bf[0][ks][0], bf[0][ks][1]);
                MMA_TF32(acc[i][1], a, bf[1][ks][0], bf[1][ks][1]);
                MMA_TF32(acc[i][2], a, bf[2][ks][0], bf[2][ks][1]);
                MMA_TF32(acc[i][3], a, bf[3][ks][0], bf[3][ks][1]);
            }
    };

    const int NCH = 1024 / 16;   // 64 per split (even)
    ldg_chunk(0);
    sts_chunk(0);
    __syncthreads();
    for (int c = 0; c < NCH; c += 2) {
        ldg_chunk(c + 1);
        compute(aA0, SB[0]);
        sts_chunk(1);
        __syncthreads();
        if (c + 2 < NCH) ldg_chunk(c + 2);
        compute(aA0 + SA_BUFB, SB[1]);
        if (c + 2 < NCH) sts_chunk(0);
        __syncthreads();
    }

    // epilogue: split 0 adds bias -> g_out2; split 1 raw -> g_out2b
    int lim = cnt - mt * 128; if (lim > 128) lim = 128;
    const float* b2e = b2 + (size_t)e * DDIM + nt * 128;
    #pragma unroll
    for (int i = 0; i < 4; i++) {
        #pragma unroll
        for (int t = 0; t < 4; t++) {
            int col = wn * 32 + t * 8 + tig * 2;
            float bA = sp ? 0.f : b2e[col];
            float bB = sp ? 0.f : b2e[col + 1];
            #pragma unroll
            for (int half = 0; half < 2; half++) {
                int r = wm * 64 + i * 16 + g + half * 8;
                if (r < lim) {
                    int pr = pid[r];
                    float* dst = sp ? &g_out2b[pr][nt * 128 + col]
                                    : &g_out2[pr][nt * 128 + col];
                    *(float2*)dst = make_float2(acc[i][t][half * 2 + 0] + bA,
                                                acc[i][t][half * 2 + 1] + bB);
                }
            }
        }
    }
}

// ---------------- combine: out = clip(x + w0*(o0a+o0b) + w1*(o1a+o1b)) ----------
__global__ void combine_kernel(const float* __restrict__ x,
                               float* __restrict__ out) {
    int i = blockIdx.x * 256 + threadIdx.x;
    int n = i >> 10;
    int d = i & 1023;
    float o0 = g_out2[2 * n + 0][d] + g_out2b[2 * n + 0][d];
    float o1 = g_out2[2 * n + 1][d] + g_out2b[2 * n + 1][d];
    float v = x[i] + g_gatew[n][0] * o0 + g_gatew[n][1] * o1;
    out[i] = fminf(fmaxf(v, -100.0f), 100.0f);
}

// ---------------- launch --------------------------------------------------------
extern "C" void kernel_launch(void* const* d_in, const int* in_sizes, int n_in,
                              void* d_out, int out_size) {
    const float* h      = (const float*)d_in[0];   // (2,1024,1024)
    const float* gate_w = (const float*)d_in[1];   // (14,1024)
    const float* w1     = (const float*)d_in[2];   // (14,1024,2048)
    const float* b1     = (const float*)d_in[3];   // (14,2048)
    const float* w2     = (const float*)d_in[4];   // (14,2048,1024)
    const float* b2     = (const float*)d_in[5];   // (14,1024)
    float* out = (float*)d_out;

    zero_kernel<<<1, 32>>>();
    gate_kernel<<<NTOK / 8, 256>>>(h, gate_w);
    prefix_kernel<<<1, 32>>>();
    gemm1_mma<<<dim3(FDIM / 128, NTOK / 128, NEXP), 256>>>(h, w1, b1);
    gemm2_mma<<<dim3(DDIM / 128, NTOK / 128, NEXP * 2), 256>>>(w2, b2);
    combine_kernel<<<(NTOK * DDIM) / 256, 256>>>(h, out);
}

// round 13
// speedup vs baseline: 2.5859x; 1.0157x over previous
#include <cuda_runtime.h>
#include <math.h>
#include <stdint.h>
#include <cuda_bf16.h>

#define NTOK 2048
#define DDIM 1024
#define NEXP 14
#define FDIM 2048
#define NPAIR (2*NTOK)
#define MPAD  (NPAIR + 128)

// ---------------- device scratch ---------------------------------------------
__device__ int   g_count[NEXP];
__device__ int   g_offset[NEXP];
__device__ int   g_pairs[NEXP][NTOK];      // value = token*2 + slot
__device__ float g_gatew[NTOK][2];
__device__ float g_h1[MPAD][FDIM];         // gemm1 output, row = offset[e]+m
__device__ float g_out2[NPAIR][DDIM];      // gemm2 partial (k-split 0, + bias)
__device__ float g_out2b[NPAIR][DDIM];     // gemm2 partial (k-split 1)

// ---------------- helpers -------------------------------------------------------
__device__ __forceinline__ uint32_t to_tf32(float f) {
    uint32_t r;
    asm("cvt.rna.tf32.f32 %0, %1;" : "=r"(r) : "f"(f));
    return r;
}
__device__ __forceinline__ uint32_t smem_u32(const void* p) {
    uint32_t a;
    asm("{ .reg .u64 t; cvta.to.shared.u64 t, %1; cvt.u32.u64 %0, t; }" : "=r"(a) : "l"(p));
    return a;
}

#define MMA_TF32(d, a, b0, b1) \
    asm volatile("mma.sync.aligned.m16n8k8.row.col.f32.tf32.tf32.f32 " \
        "{%0,%1,%2,%3},{%4,%5,%6,%7},{%8,%9},{%0,%1,%2,%3};" \
        : "+f"((d)[0]), "+f"((d)[1]), "+f"((d)[2]), "+f"((d)[3]) \
        : "r"((a)[0]), "r"((a)[1]), "r"((a)[2]), "r"((a)[3]), "r"(b0), "r"(b1))

#define LDSM4(r, addr) \
    asm volatile("ldmatrix.sync.aligned.m8n8.x4.shared.b16 {%0,%1,%2,%3}, [%4];" \
        : "=r"((r)[0]), "=r"((r)[1]), "=r"((r)[2]), "=r"((r)[3]) : "r"(addr))

#define CP16(d, s) \
    asm volatile("cp.async.cg.shared.global [%0], [%1], 16;" :: "r"(d), "l"(s) : "memory")
#define CP_COMMIT() asm volatile("cp.async.commit_group;" ::: "memory")
#define CP_WAIT1()  asm volatile("cp.async.wait_group 1;" ::: "memory")
#define CP_WAIT0()  asm volatile("cp.async.wait_group 0;" ::: "memory")

// ---------------- kernel: zero expert counts ----------------------------------
__global__ void zero_kernel() {
    if (threadIdx.x < NEXP) g_count[threadIdx.x] = 0;
}

// ---------------- kernel: gating — warp per token, shuffle reductions ----------
__global__ void gate_kernel(const float* __restrict__ x,
                            const float* __restrict__ gw) {
    int lane = threadIdx.x & 31, wid = threadIdx.x >> 5;
    int n = blockIdx.x * 8 + wid;
    const float4* xr = (const float4*)(x + (size_t)n * DDIM);
    float4 xv[8];
    #pragma unroll
    for (int i = 0; i < 8; i++) xv[i] = xr[i * 32 + lane];

    float l0 = -3.0e38f, l1 = -3.0e38f;
    int i0 = 0, i1 = -1;
    for (int e = 0; e < NEXP; e++) {
        const float4* we = (const float4*)(gw + (size_t)e * DDIM);
        float s = 0.f;
        #pragma unroll
        for (int i = 0; i < 8; i++) {
            float4 b = we[i * 32 + lane];
            s += xv[i].x * b.x + xv[i].y * b.y + xv[i].z * b.z + xv[i].w * b.w;
        }
        #pragma unroll
        for (int o = 16; o; o >>= 1) s += __shfl_xor_sync(0xFFFFFFFFu, s, o);
        if (s > l0)      { l1 = l0; i1 = i0; l0 = s; i0 = e; }
        else if (s > l1) { l1 = s;  i1 = e; }
    }
    if (lane == 0) {
        float p1 = expf(l1 - l0);
        float inv = 1.0f / (1.0f + p1);
        g_gatew[n][0] = inv;
        g_gatew[n][1] = p1 * inv;
        int s0 = atomicAdd(&g_count[i0], 1);
        g_pairs[i0][s0] = n * 2 + 0;
        int s1 = atomicAdd(&g_count[i1], 1);
        g_pairs[i1][s1] = n * 2 + 1;
    }
}

__global__ void prefix_kernel() {
    if (threadIdx.x == 0) {
        int s = 0;
        for (int e = 0; e < NEXP; e++) { g_offset[e] = s; s += g_count[e]; }
    }
}

// =================================================================================
// TF32 GEMM — A: LDG + cvt.rna + STS, double-buffered (proven).
//             B: cp.async 3-buffer ring (raw tf32-truncated weights).
//   SA[2]: [128 m][20 u32] (80B stride), frags via ldmatrix.x4.
//   SB[3]: [16 k][136 u32] (544B stride), frags via scalar LDS (conflict-free).
//   Ring safety: B(c+2)->buf (c+2)%3 issued at top of phase c; that buf was last
//   read in phase c-1 whose barrier has completed. One __syncthreads per chunk.
//   8 warps = 2(m) x 4(n); warp tile 64x32; m16n8k8 tf32, fp32 accum.
// =================================================================================
#define SA_BUFB 10240u   // 128*20*4
#define SB_BUFB 8704u    // 16*136*4

// ---------------- GEMM1: h1 = gelu(x_gathered @ w1 + b1) -------------------------
__global__ void __launch_bounds__(256, 2)
gemm1_mma(const float* __restrict__ x,
          const float* __restrict__ w1,
          const float* __restrict__ b1) {
    int e = blockIdx.z, mt = blockIdx.y;
    int cnt = g_count[e];
    if (mt * 128 >= cnt) return;
    int nt = blockIdx.x;
    int off = g_offset[e];

    __shared__ __align__(16) uint32_t SA[2][128][20];
    __shared__ __align__(16) uint32_t SB[3][16][136];
    __shared__ int rowtok[128];

    int tid = threadIdx.x, lane = tid & 31, wid = tid >> 5;
    int wm = wid & 1, wn = wid >> 1;
    int g = lane >> 2, tig = lane & 3;

    if (tid < 128) {
        int m = mt * 128 + tid;
        rowtok[tid] = (m < cnt) ? (g_pairs[e][m] >> 1) : -1;
    }
    __syncthreads();

    int lm = tid & 127, kh = tid >> 7;
    int tok = rowtok[lm];
    const float* xrow = x + (size_t)(tok < 0 ? 0 : tok) * DDIM + kh * 8;
    int bk = tid >> 5, bn = (tid & 31) * 4;
    const float* w1e = w1 + (size_t)e * DDIM * FDIM + nt * 128;
    const float* bsrc = w1e + (size_t)bk * FDIM + bn;

    float4 ra0, ra1;
    auto ldgA = [&](int c) {
        int k0 = c * 16;
        if (tok >= 0) {
            ra0 = *(const float4*)(xrow + k0);
            ra1 = *(const float4*)(xrow + k0 + 4);
        } else {
            ra0 = make_float4(0.f, 0.f, 0.f, 0.f); ra1 = ra0;
        }
    };
    auto stsA = [&](int buf) {
        *(uint4*)&SA[buf][lm][kh * 8] =
            make_uint4(to_tf32(ra0.x), to_tf32(ra0.y), to_tf32(ra0.z), to_tf32(ra0.w));
        *(uint4*)&SA[buf][lm][kh * 8 + 4] =
            make_uint4(to_tf32(ra1.x), to_tf32(ra1.y), to_tf32(ra1.z), to_tf32(ra1.w));
    };
    auto cpB = [&](int c, uint32_t d0, uint32_t d8) {
        const float* s = bsrc + (size_t)(c * 16) * FDIM;
        CP16(d0, s);
        CP16(d8, s + (size_t)8 * FDIM);
        CP_COMMIT();
    };

    uint32_t aA0 = smem_u32(&SA[0][0][0]) + (wm * 64 + (lane & 15)) * 80 + (lane >> 4) * 16;
    int bn0 = wn * 32 + (lane >> 2);
    int bk0 = lane & 3;

    float acc[4][4][4] = {};

    auto compute = [&](uint32_t aAb, const uint32_t (*sB)[136]) {
        uint32_t bf[4][2][2];
        #pragma unroll
        for (int t = 0; t < 4; t++)
            #pragma unroll
            for (int ks = 0; ks < 2; ks++) {
                bf[t][ks][0] = sB[ks * 8 + bk0][bn0 + t * 8];
                bf[t][ks][1] = sB[ks * 8 + bk0 + 4][bn0 + t * 8];
            }
        #pragma unroll
        for (int ks = 0; ks < 2; ks++)
            #pragma unroll
            for (int i = 0; i < 4; i++) {
                uint32_t a[4];
                LDSM4(a, aAb + ks * 32 + i * 1280);
                MMA_TF32(acc[i][0], a, bf[0][ks][0], bf[0][ks][1]);
                MMA_TF32(acc[i][1], a, bf[1][ks][0], bf[1][ks][1]);
                MMA_TF32(acc[i][2], a, bf[2][ks][0], bf[2][ks][1]);
                MMA_TF32(acc[i][3], a, bf[3][ks][0], bf[3][ks][1]);
            }
    };

    const int NCH = DDIM / 16;   // 64
    // prologue: B chunks 0,1 in flight; A chunk 0 staged
    cpB(0, smem_u32(&SB[0][bk][bn]), smem_u32(&SB[0][bk + 8][bn]));
    cpB(1, smem_u32(&SB[1][bk][bn]), smem_u32(&SB[1][bk + 8][bn]));
    ldgA(0);
    stsA(0);
    CP_WAIT1();            // B0 arrived
    __syncthreads();

    uint32_t wrB0 = smem_u32(&SB[2][bk][bn]);
    uint32_t wrB8 = smem_u32(&SB[2][bk + 8][bn]);
    const uint32_t wrHi = wrB0;
    const uint32_t (*rdB)[136] = SB[0];
    uint32_t aOff = 0;
    int aBuf = 1;

    for (int c = 0; c < NCH; c++) {
        if (c + 2 < NCH) {
            cpB(c + 2, wrB0, wrB8);
            wrB0 += SB_BUFB; wrB8 += SB_BUFB;
            if (wrB0 > wrHi) { wrB0 -= 3 * SB_BUFB; wrB8 -= 3 * SB_BUFB; }
        }
        if (c + 1 < NCH) ldgA(c + 1);
        compute(aA0 + aOff, rdB);
        if (c + 1 < NCH) stsA(aBuf);
        if (c + 2 < NCH) CP_WAIT1();
        else if (c + 1 < NCH) CP_WAIT0();
        __syncthreads();
        aOff ^= SA_BUFB;
        aBuf ^= 1;
        rdB = (rdB == SB[2]) ? SB[0] : rdB + 16;
    }

    // epilogue: bias + exact gelu, fp32 store to g_h1
    int lim = cnt - mt * 128; if (lim > 128) lim = 128;
    const float* b1e = b1 + (size_t)e * FDIM + nt * 128;
    #pragma unroll
    for (int i = 0; i < 4; i++) {
        #pragma unroll
        for (int t = 0; t < 4; t++) {
            int col = wn * 32 + t * 8 + tig * 2;
            float bA = b1e[col], bB = b1e[col + 1];
            #pragma unroll
            for (int half = 0; half < 2; half++) {
                int r = wm * 64 + i * 16 + g + half * 8;
                if (r < lim) {
                    float v0 = acc[i][t][half * 2 + 0] + bA;
                    float v1 = acc[i][t][half * 2 + 1] + bB;
                    v0 = 0.5f * v0 * (1.0f + erff(v0 * 0.70710678118654752440f));
                    v1 = 0.5f * v1 * (1.0f + erff(v1 * 0.70710678118654752440f));
                    *(float2*)&g_h1[off + mt * 128 + r][nt * 128 + col] =
                        make_float2(v0, v1);
                }
            }
        }
    }
}

// ---------------- GEMM2 (split-K x2): out2[s] = h1[:, sK:] @ w2[sK:, :] ----------
__global__ void __launch_bounds__(256, 2)
gemm2_mma(const float* __restrict__ w2,
          const float* __restrict__ b2) {
    int ez = blockIdx.z;
    int e = ez >> 1, sp = ez & 1;
    int mt = blockIdx.y;
    int cnt = g_count[e];
    if (mt * 128 >= cnt) return;
    int nt = blockIdx.x;
    int off = g_offset[e];
    int mrow0 = off + mt * 128;

    __shared__ __align__(16) uint32_t SA[2][128][20];
    __shared__ __align__(16) uint32_t SB[3][16][136];
    __shared__ int pid[128];

    int tid = threadIdx.x, lane = tid & 31, wid = tid >> 5;
    int wm = wid & 1, wn = wid >> 1;
    int g = lane >> 2, tig = lane & 3;

    if (tid < 128) {
        int m = mt * 128 + tid;
        pid[tid] = (m < cnt) ? g_pairs[e][m] : 0;
    }
    __syncthreads();

    int lm = tid & 127, kh = tid >> 7;
    const float* arow = &g_h1[mrow0 + lm][sp * 1024 + kh * 8];
    int bk = tid >> 5, bn = (tid & 31) * 4;
    const float* w2e = w2 + (size_t)e * FDIM * DDIM + nt * 128;
    const float* bsrc = w2e + (size_t)(sp * 1024 + bk) * DDIM + bn;

    float4 ra0, ra1;
    auto ldgA = [&](int c) {
        int k0 = c * 16;
        ra0 = *(const float4*)(arow + k0);
        ra1 = *(const float4*)(arow + k0 + 4);
    };
    auto stsA = [&](int buf) {
        *(uint4*)&SA[buf][lm][kh * 8] =
            make_uint4(to_tf32(ra0.x), to_tf32(ra0.y), to_tf32(ra0.z), to_tf32(ra0.w));
        *(uint4*)&SA[buf][lm][kh * 8 + 4] =
            make_uint4(to_tf32(ra1.x), to_tf32(ra1.y), to_tf32(ra1.z), to_tf32(ra1.w));
    };
    auto cpB = [&](int c, uint32_t d0, uint32_t d8) {
        const float* s = bsrc + (size_t)(c * 16) * DDIM;
        CP16(d0, s);
        CP16(d8, s + (size_t)8 * DDIM);
        CP_COMMIT();
    };

    uint32_t aA0 = smem_u32(&SA[0][0][0]) + (wm * 64 + (lane & 15)) * 80 + (lane >> 4) * 16;
    int bn0 = wn * 32 + (lane >> 2);
    int bk0 = lane & 3;

    float acc[4][4][4] = {};

    auto compute = [&](uint32_t aAb, const uint32_t (*sB)[136]) {
        uint32_t bf[4][2][2];
        #pragma unroll
        for (int t = 0; t < 4; t++)
            #pragma unroll
            for (int ks = 0; ks < 2; ks++) {
                bf[t][ks][0] = sB[ks * 8 + bk0][bn0 + t * 8];
                bf[t][ks][1] = sB[ks * 8 + bk0 + 4][bn0 + t * 8];
            }
        #pragma unroll
        for (int ks = 0; ks < 2; ks++)
            #pragma unroll
            for (int i = 0; i < 4; i++) {
                uint32_t a[4];
                LDSM4(a, aAb + ks * 32 + i * 1280);
                MMA_TF32(acc[i][0], a, bf[0][ks][0], bf[0][ks][1]);
                MMA_TF32(acc[i][1], a, bf[1][ks][0], bf[1][ks][1]);
                MMA_TF32(acc[i][2], a, bf[2][ks][0], bf[2][ks][1]);
                MMA_TF32(acc[i][3], a, bf[3][ks][0], bf[3][ks][1]);
            }
    };

    const int NCH = 1024 / 16;   // 64 per split
    cpB(0, smem_u32(&SB[0][bk][bn]), smem_u32(&SB[0][bk + 8][bn]));
    cpB(1, smem_u32(&SB[1][bk][bn]), smem_u32(&SB[1][bk + 8][bn]));
    ldgA(0);
    stsA(0);
    CP_WAIT1();
    __syncthreads();

    uint32_t wrB0 = smem_u32(&SB[2][bk][bn]);
    uint32_t wrB8 = smem_u32(&SB[2][bk + 8][bn]);
    const uint32_t wrHi = wrB0;
    const uint32_t (*rdB)[136] = SB[0];
    uint32_t aOff = 0;
    int aBuf = 1;

    for (int c = 0; c < NCH; c++) {
        if (c + 2 < NCH) {
            cpB(c + 2, wrB0, wrB8);
            wrB0 += SB_BUFB; wrB8 += SB_BUFB;
            if (wrB0 > wrHi) { wrB0 -= 3 * SB_BUFB; wrB8 -= 3 * SB_BUFB; }
        }
        if (c + 1 < NCH) ldgA(c + 1);
        compute(aA0 + aOff, rdB);
        if (c + 1 < NCH) stsA(aBuf);
        if (c + 2 < NCH) CP_WAIT1();
        else if (c + 1 < NCH) CP_WAIT0();
        __syncthreads();
        aOff ^= SA_BUFB;
        aBuf ^= 1;
        rdB = (rdB == SB[2]) ? SB[0] : rdB + 16;
    }

    // epilogue: split 0 adds bias -> g_out2; split 1 raw -> g_out2b
    int lim = cnt - mt * 128; if (lim > 128) lim = 128;
    const float* b2e = b2 + (size_t)e * DDIM + nt * 128;
    #pragma unroll
    for (int i = 0; i < 4; i++) {
        #pragma unroll
        for (int t = 0; t < 4; t++) {
            int col = wn * 32 + t * 8 + tig * 2;
            float bA = sp ? 0.f : b2e[col];
            float bB = sp ? 0.f : b2e[col + 1];
            #pragma unroll
            for (int half = 0; half < 2; half++) {
                int r = wm * 64 + i * 16 + g + half * 8;
                if (r < lim) {
                    int pr = pid[r];
                    float* dst = sp ? &g_out2b[pr][nt * 128 + col]
                                    : &g_out2[pr][nt * 128 + col];
                    *(float2*)dst = make_float2(acc[i][t][half * 2 + 0] + bA,
                                                acc[i][t][half * 2 + 1] + bB);
                }
            }
        }
    }
}

// ---------------- combine: out = clip(x + w0*(o0a+o0b) + w1*(o1a+o1b)) ----------
__global__ void combine_kernel(const float* __restrict__ x,
                               float* __restrict__ out) {
    int i = blockIdx.x * 256 + threadIdx.x;
    int n = i >> 10;
    int d = i & 1023;
    float o0 = g_out2[2 * n + 0][d] + g_out2b[2 * n + 0][d];
    float o1 = g_out2[2 * n + 1][d] + g_out2b[2 * n + 1][d];
    float v = x[i] + g_gatew[n][0] * o0 + g_gatew[n][1] * o1;
    out[i] = fminf(fmaxf(v, -100.0f), 100.0f);
}

// ---------------- launch --------------------------------------------------------
extern "C" void kernel_launch(void* const* d_in, const int* in_sizes, int n_in,
                              void* d_out, int out_size) {
    const float* h      = (const float*)d_in[0];   // (2,1024,1024)
    const float* gate_w = (const float*)d_in[1];   // (14,1024)
    const float* w1     = (const float*)d_in[2];   // (14,1024,2048)
    const float* b1     = (const float*)d_in[3];   // (14,2048)
    const float* w2     = (const float*)d_in[4];   // (14,2048,1024)
    const float* b2     = (const float*)d_in[5];   // (14,1024)
    float* out = (float*)d_out;

    zero_kernel<<<1, 32>>>();
    gate_kernel<<<NTOK / 8, 256>>>(h, gate_w);
    prefix_kernel<<<1, 32>>>();
    gemm1_mma<<<dim3(FDIM / 128, NTOK / 128, NEXP), 256>>>(h, w1, b1);
    gemm2_mma<<<dim3(DDIM / 128, NTOK / 128, NEXP * 2), 256>>>(w2, b2);
    combine_kernel<<<(NTOK * DDIM) / 256, 256>>>(h, out);
}

// round 14
// speedup vs baseline: 2.9147x; 1.1272x over previous
#include <cuda_runtime.h>
#include <math.h>
#include <stdint.h>
#include <cuda_bf16.h>

#define NTOK 2048
#define DDIM 1024
#define NEXP 14
#define FDIM 2048
#define NPAIR (2*NTOK)
#define MPAD  (NPAIR + 128)

// ---------------- device scratch ---------------------------------------------
__device__ int   g_count[NEXP];
__device__ int   g_offset[NEXP];
__device__ int   g_pairs[NEXP][NTOK];      // value = token*2 + slot
__device__ int   g_sorted[NPAIR];
__device__ float g_gatew[NTOK][2];
__device__ __align__(128) float g_xs[MPAD][DDIM];   // gathered x, tf32-rounded
__device__ __align__(128) float g_h1[MPAD][FDIM];   // gemm1 out, tf32-rounded
__device__ __align__(128) float g_out2[NPAIR][DDIM];  // split 0 (+bias)
__device__ __align__(128) float g_out2b[NPAIR][DDIM]; // split 1

// ---------------- helpers -------------------------------------------------------
__device__ __forceinline__ uint32_t to_tf32(float f) {
    uint32_t r;
    asm("cvt.rna.tf32.f32 %0, %1;" : "=r"(r) : "f"(f));
    return r;
}
__device__ __forceinline__ uint32_t smem_u32(const void* p) {
    uint32_t a;
    asm("{ .reg .u64 t; cvta.to.shared.u64 t, %1; cvt.u32.u64 %0, t; }" : "=r"(a) : "l"(p));
    return a;
}

#define MMA_TF32(d, a, b0, b1) \
    asm volatile("mma.sync.aligned.m16n8k8.row.col.f32.tf32.tf32.f32 " \
        "{%0,%1,%2,%3},{%4,%5,%6,%7},{%8,%9},{%0,%1,%2,%3};" \
        : "+f"((d)[0]), "+f"((d)[1]), "+f"((d)[2]), "+f"((d)[3]) \
        : "r"((a)[0]), "r"((a)[1]), "r"((a)[2]), "r"((a)[3]), "r"(b0), "r"(b1))

#define LDSM4(r, addr) \
    asm volatile("ldmatrix.sync.aligned.m8n8.x4.shared.b16 {%0,%1,%2,%3}, [%4];" \
        : "=r"((r)[0]), "=r"((r)[1]), "=r"((r)[2]), "=r"((r)[3]) : "r"(addr))

#define CP16(d, s) \
    asm volatile("cp.async.cg.shared.global [%0], [%1], 16;" :: "r"(d), "l"(s) : "memory")
#define CP_COMMIT() asm volatile("cp.async.commit_group;" ::: "memory")
#define CP_WAIT1()  asm volatile("cp.async.wait_group 1;" ::: "memory")
#define CP_WAIT0()  asm volatile("cp.async.wait_group 0;" ::: "memory")

// ---------------- kernel: zero expert counts ----------------------------------
__global__ void zero_kernel() {
    if (threadIdx.x < NEXP) g_count[threadIdx.x] = 0;
}

// ---------------- kernel: gating — warp per token, shuffle reductions ----------
__global__ void gate_kernel(const float* __restrict__ x,
                            const float* __restrict__ gw) {
    int lane = threadIdx.x & 31, wid = threadIdx.x >> 5;
    int n = blockIdx.x * 8 + wid;
    const float4* xr = (const float4*)(x + (size_t)n * DDIM);
    float4 xv[8];
    #pragma unroll
    for (int i = 0; i < 8; i++) xv[i] = xr[i * 32 + lane];

    float l0 = -3.0e38f, l1 = -3.0e38f;
    int i0 = 0, i1 = -1;
    for (int e = 0; e < NEXP; e++) {
        const float4* we = (const float4*)(gw + (size_t)e * DDIM);
        float s = 0.f;
        #pragma unroll
        for (int i = 0; i < 8; i++) {
            float4 b = we[i * 32 + lane];
            s += xv[i].x * b.x + xv[i].y * b.y + xv[i].z * b.z + xv[i].w * b.w;
        }
        #pragma unroll
        for (int o = 16; o; o >>= 1) s += __shfl_xor_sync(0xFFFFFFFFu, s, o);
        if (s > l0)      { l1 = l0; i1 = i0; l0 = s; i0 = e; }
        else if (s > l1) { l1 = s;  i1 = e; }
    }
    if (lane == 0) {
        float p1 = expf(l1 - l0);
        float inv = 1.0f / (1.0f + p1);
        g_gatew[n][0] = inv;
        g_gatew[n][1] = p1 * inv;
        int s0 = atomicAdd(&g_count[i0], 1);
        g_pairs[i0][s0] = n * 2 + 0;
        int s1 = atomicAdd(&g_count[i1], 1);
        g_pairs[i1][s1] = n * 2 + 1;
    }
}

__global__ void prefix_kernel() {
    if (threadIdx.x == 0) {
        int s = 0;
        for (int e = 0; e < NEXP; e++) { g_offset[e] = s; s += g_count[e]; }
    }
}

__global__ void sort_kernel() {
    int e = blockIdx.y;
    int i = blockIdx.x * 256 + threadIdx.x;
    if (i < g_count[e]) g_sorted[g_offset[e] + i] = g_pairs[e][i];
}

// gather routed x rows expert-sorted, tf32-rounded; zero-pad tail rows
__global__ void gather_x(const float* __restrict__ x) {
    int row = blockIdx.x;                  // 0..MPAD-1
    int tid = threadIdx.x;                 // 256 threads, 1 float4 each
    float4 v = make_float4(0.f, 0.f, 0.f, 0.f);
    if (row < NPAIR) {
        int tok = g_sorted[row] >> 1;
        v = ((const float4*)(x + (size_t)tok * DDIM))[tid];
    }
    uint4 r = make_uint4(to_tf32(v.x), to_tf32(v.y), to_tf32(v.z), to_tf32(v.w));
    ((uint4*)(g_xs[row]))[tid] = r;
}

// =================================================================================
// TF32 GEMM — all operands via cp.async (A pre-rounded in gmem, B raw-truncated).
//   SA[2]: [128 m][20 u32] (80B stride), frags via ldmatrix.x4 (proven).
//   SB[3]: [16 k][136 u32] (544B stride), frags via scalar LDS (proven).
//   Per-phase group order: [A(c+1)], [B(c+2)]; wait_group 1 at phase top ->
//   A(c) + B(c) complete, B(c+1) may remain in flight (depth-2 covers DRAM).
//   Ring safety: A(c+1)->slot (c+1)%2 (slot read last in phase c-1, barrier done);
//   B(c+2)->slot (c+2)%3 (read last in phase c-1). Chunk index clamped at tail.
//   8 warps = 2(m) x 4(n); warp tile 64x32; m16n8k8 tf32, fp32 accum.
// =================================================================================
#define SA_BUFB 10240u   // 128*20*4
#define SB_BUFB 8704u    // 16*136*4

// ---------------- GEMM1: h1 = gelu(g_xs @ w1 + b1), tf32-rounded store ----------
__global__ void __launch_bounds__(256, 2)
gemm1_mma(const float* __restrict__ w1,
          const float* __restrict__ b1) {
    int e = blockIdx.z, mt = blockIdx.y;
    int cnt = g_count[e];
    if (mt * 128 >= cnt) return;
    int nt = blockIdx.x;
    int off = g_offset[e];
    int mrow0 = off + mt * 128;

    __shared__ __align__(16) uint32_t SA[2][128][20];
    __shared__ __align__(16) uint32_t SB[3][16][136];

    int tid = threadIdx.x, lane = tid & 31, wid = tid >> 5;
    int wm = wid & 1, wn = wid >> 1;
    int g = lane >> 2, tig = lane & 3;

    // A loader: row lm, k-half kh (8 floats = 2x16B)
    int lm = tid & 127, kh = tid >> 7;
    const float* arow = &g_xs[mrow0 + lm][kh * 8];
    uint32_t dA0 = smem_u32(&SA[0][lm][kh * 8]);
    // B loader: rows bk, bk+8; 4-float group bn
    int bk = tid >> 5, bn = (tid & 31) * 4;
    const float* bsrc = w1 + (size_t)e * DDIM * FDIM + (size_t)bk * FDIM + nt * 128 + bn;
    uint32_t dB0 = smem_u32(&SB[0][bk][bn]);

    auto cpA = [&](int c, int slot) {
        const float* s = arow + (size_t)c * 16;
        uint32_t d = dA0 + slot * SA_BUFB;
        CP16(d, s);
        CP16(d + 16, s + 4);
        CP_COMMIT();
    };
    auto cpB = [&](int c, uint32_t d) {
        const float* s = bsrc + (size_t)(c * 16) * FDIM;
        CP16(d, s);
        CP16(d + 8 * 544, s + (size_t)8 * FDIM);
        CP_COMMIT();
    };

    uint32_t aA0 = smem_u32(&SA[0][0][0]) + (wm * 64 + (lane & 15)) * 80 + (lane >> 4) * 16;
    int bn0 = wn * 32 + (lane >> 2);
    int bk0 = lane & 3;

    float acc[4][4][4] = {};

    auto compute = [&](uint32_t aAb, const uint32_t (*sB)[136]) {
        uint32_t bf[4][2][2];
        #pragma unroll
        for (int t = 0; t < 4; t++)
            #pragma unroll
            for (int ks = 0; ks < 2; ks++) {
                bf[t][ks][0] = sB[ks * 8 + bk0][bn0 + t * 8];
                bf[t][ks][1] = sB[ks * 8 + bk0 + 4][bn0 + t * 8];
            }
        #pragma unroll
        for (int ks = 0; ks < 2; ks++)
            #pragma unroll
            for (int i = 0; i < 4; i++) {
                uint32_t a[4];
                LDSM4(a, aAb + ks * 32 + i * 1280);
                MMA_TF32(acc[i][0], a, bf[0][ks][0], bf[0][ks][1]);
                MMA_TF32(acc[i][1], a, bf[1][ks][0], bf[1][ks][1]);
                MMA_TF32(acc[i][2], a, bf[2][ks][0], bf[2][ks][1]);
                MMA_TF32(acc[i][3], a, bf[3][ks][0], bf[3][ks][1]);
            }
    };

    const int NCH = DDIM / 16;   // 64
    // prologue (issue order matters for wait_group accounting): A0, B0, B1
    cpA(0, 0);
    cpB(0, dB0);
    cpB(1, dB0 + SB_BUFB);

    uint32_t wrB = dB0 + 2 * SB_BUFB;          // next B write slot (slot 2)
    const uint32_t wrBhi = dB0 + 2 * SB_BUFB;
    const uint32_t (*rdB)[136] = SB[0];
    uint32_t aOff = 0;

    for (int c = 0; c < NCH; c++) {
        CP_WAIT1();                 // A(c), B(c) complete; B(c+1) may be in flight
        __syncthreads();
        int ca = c + 1 < NCH ? c + 1 : NCH - 1;
        int cb = c + 2 < NCH ? c + 2 : NCH - 1;
        cpA(ca, (c + 1) & 1);
        cpB(cb, wrB);
        wrB += SB_BUFB;
        if (wrB > wrBhi) wrB -= 3 * SB_BUFB;
        compute(aA0 + aOff, rdB);
        aOff ^= SA_BUFB;
        rdB = (rdB == SB[2]) ? SB[0] : rdB + 16;
    }
    CP_WAIT0();

    // epilogue: bias + exact gelu, tf32-rounded store to g_h1
    int lim = cnt - mt * 128; if (lim > 128) lim = 128;
    const float* b1e = b1 + (size_t)e * FDIM + nt * 128;
    #pragma unroll
    for (int i = 0; i < 4; i++) {
        #pragma unroll
        for (int t = 0; t < 4; t++) {
            int col = wn * 32 + t * 8 + tig * 2;
            float bA = b1e[col], bB = b1e[col + 1];
            #pragma unroll
            for (int half = 0; half < 2; half++) {
                int r = wm * 64 + i * 16 + g + half * 8;
                if (r < lim) {
                    float v0 = acc[i][t][half * 2 + 0] + bA;
                    float v1 = acc[i][t][half * 2 + 1] + bB;
                    v0 = 0.5f * v0 * (1.0f + erff(v0 * 0.70710678118654752440f));
                    v1 = 0.5f * v1 * (1.0f + erff(v1 * 0.70710678118654752440f));
                    *(float2*)&g_h1[mrow0 + r][nt * 128 + col] =
                        make_float2(__uint_as_float(to_tf32(v0)),
                                    __uint_as_float(to_tf32(v1)));
                }
            }
        }
    }
}

// ---------------- GEMM2 (split-K x2): out2[s] = h1[:, sK:] @ w2[sK:, :] ----------
__global__ void __launch_bounds__(256, 2)
gemm2_mma(const float* __restrict__ w2,
          const float* __restrict__ b2) {
    int ez = blockIdx.z;
    int e = ez >> 1, sp = ez & 1;
    int mt = blockIdx.y;
    int cnt = g_count[e];
    if (mt * 128 >= cnt) return;
    int nt = blockIdx.x;
    int off = g_offset[e];
    int mrow0 = off + mt * 128;

    __shared__ __align__(16) uint32_t SA[2][128][20];
    __shared__ __align__(16) uint32_t SB[3][16][136];
    __shared__ int pid[128];

    int tid = threadIdx.x, lane = tid & 31, wid = tid >> 5;
    int wm = wid & 1, wn = wid >> 1;
    int g = lane >> 2, tig = lane & 3;

    if (tid < 128) {
        int m = mt * 128 + tid;
        pid[tid] = (m < cnt) ? g_pairs[e][m] : 0;
    }
    __syncthreads();

    int lm = tid & 127, kh = tid >> 7;
    const float* arow = &g_h1[mrow0 + lm][sp * 1024 + kh * 8];
    uint32_t dA0 = smem_u32(&SA[0][lm][kh * 8]);
    int bk = tid >> 5, bn = (tid & 31) * 4;
    const float* bsrc = w2 + (size_t)e * FDIM * DDIM
                      + (size_t)(sp * 1024 + bk) * DDIM + nt * 128 + bn;
    uint32_t dB0 = smem_u32(&SB[0][bk][bn]);

    auto cpA = [&](int c, int slot) {
        const float* s = arow + (size_t)c * 16;
        uint32_t d = dA0 + slot * SA_BUFB;
        CP16(d, s);
        CP16(d + 16, s + 4);
        CP_COMMIT();
    };
    auto cpB = [&](int c, uint32_t d) {
        const float* s = bsrc + (size_t)(c * 16) * DDIM;
        CP16(d, s);
        CP16(d + 8 * 544, s + (size_t)8 * DDIM);
        CP_COMMIT();
    };

    uint32_t aA0 = smem_u32(&SA[0][0][0]) + (wm * 64 + (lane & 15)) * 80 + (lane >> 4) * 16;
    int bn0 = wn * 32 + (lane >> 2);
    int bk0 = lane & 3;

    float acc[4][4][4] = {};

    auto compute = [&](uint32_t aAb, const uint32_t (*sB)[136]) {
        uint32_t bf[4][2][2];
        #pragma unroll
        for (int t = 0; t < 4; t++)
            #pragma unroll
            for (int ks = 0; ks < 2; ks++) {
                bf[t][ks][0] = sB[ks * 8 + bk0][bn0 + t * 8];
                bf[t][ks][1] = sB[ks * 8 + bk0 + 4][bn0 + t * 8];
            }
        #pragma unroll
        for (int ks = 0; ks < 2; ks++)
            #pragma unroll
            for (int i = 0; i < 4; i++) {
                uint32_t a[4];
                LDSM4(a, aAb + ks * 32 + i * 1280);
                MMA_TF32(acc[i][0], a, bf[0][ks][0], bf[0][ks][1]);
                MMA_TF32(acc[i][1], a, bf[1][ks][0], bf[1][ks][1]);
                MMA_TF32(acc[i][2], a, bf[2][ks][0], bf[2][ks][1]);
                MMA_TF32(acc[i][3], a, bf[3][ks][0], bf[3][ks][1]);
            }
    };

    const int NCH = 1024 / 16;   // 64 per split
    cpA(0, 0);
    cpB(0, dB0);
    cpB(1, dB0 + SB_BUFB);

    uint32_t wrB = dB0 + 2 * SB_BUFB;
    const uint32_t wrBhi = dB0 + 2 * SB_BUFB;
    const uint32_t (*rdB)[136] = SB[0];
    uint32_t aOff = 0;

    for (int c = 0; c < NCH; c++) {
        CP_WAIT1();
        __syncthreads();
        int ca = c + 1 < NCH ? c + 1 : NCH - 1;
        int cb = c + 2 < NCH ? c + 2 : NCH - 1;
        cpA(ca, (c + 1) & 1);
        cpB(cb, wrB);
        wrB += SB_BUFB;
        if (wrB > wrBhi) wrB -= 3 * SB_BUFB;
        compute(aA0 + aOff, rdB);
        aOff ^= SA_BUFB;
        rdB = (rdB == SB[2]) ? SB[0] : rdB + 16;
    }
    CP_WAIT0();

    // epilogue: split 0 adds bias -> g_out2; split 1 raw -> g_out2b
    int lim = cnt - mt * 128; if (lim > 128) lim = 128;
    const float* b2e = b2 + (size_t)e * DDIM + nt * 128;
    #pragma unroll
    for (int i = 0; i < 4; i++) {
        #pragma unroll
        for (int t = 0; t < 4; t++) {
            int col = wn * 32 + t * 8 + tig * 2;
            float bA = sp ? 0.f : b2e[col];
            float bB = sp ? 0.f : b2e[col + 1];
            #pragma unroll
            for (int half = 0; half < 2; half++) {
                int r = wm * 64 + i * 16 + g + half * 8;
                if (r < lim) {
                    int pr = pid[r];
                    float* dst = sp ? &g_out2b[pr][nt * 128 + col]
                                    : &g_out2[pr][nt * 128 + col];
                    *(float2*)dst = make_float2(acc[i][t][half * 2 + 0] + bA,
                                                acc[i][t][half * 2 + 1] + bB);
                }
            }
        }
    }
}

// ---------------- combine: out = clip(x + w0*(o0a+o0b) + w1*(o1a+o1b)) ----------
__global__ void combine_kernel(const float* __restrict__ x,
                               float* __restrict__ out) {
    int i = blockIdx.x * 256 + threadIdx.x;
    int n = i >> 10;
    int d = i & 1023;
    float o0 = g_out2[2 * n + 0][d] + g_out2b[2 * n + 0][d];
    float o1 = g_out2[2 * n + 1][d] + g_out2b[2 * n + 1][d];
    float v = x[i] + g_gatew[n][0] * o0 + g_gatew[n][1] * o1;
    out[i] = fminf(fmaxf(v, -100.0f), 100.0f);
}

// ---------------- launch --------------------------------------------------------
extern "C" void kernel_launch(void* const* d_in, const int* in_sizes, int n_in,
                              void* d_out, int out_size) {
    const float* h      = (const float*)d_in[0];   // (2,1024,1024)
    const float* gate_w = (const float*)d_in[1];   // (14,1024)
    const float* w1     = (const float*)d_in[2];   // (14,1024,2048)
    const float* b1     = (const float*)d_in[3];   // (14,2048)
    const float* w2     = (const float*)d_in[4];   // (14,2048,1024)
    const float* b2     = (const float*)d_in[5];   // (14,1024)
    float* out = (float*)d_out;

    zero_kernel<<<1, 32>>>();
    gate_kernel<<<NTOK / 8, 256>>>(h, gate_w);
    prefix_kernel<<<1, 32>>>();
    sort_kernel<<<dim3(NTOK / 256, NEXP), 256>>>();
    gather_x<<<MPAD, 256>>>(h);
    gemm1_mma<<<dim3(FDIM / 128, NTOK / 128, NEXP), 256>>>(w1, b1);
    gemm2_mma<<<dim3(DDIM / 128, NTOK / 128, NEXP * 2), 256>>>(w2, b2);
    combine_kernel<<<(NTOK * DDIM) / 256, 256>>>(h, out);
}

// round 15
// speedup vs baseline: 3.0015x; 1.0298x over previous
#include <cuda_runtime.h>
#include <math.h>
#include <stdint.h>
#include <cuda_bf16.h>

#define NTOK 2048
#define DDIM 1024
#define NEXP 14
#define FDIM 2048
#define NPAIR (2*NTOK)
#define MPAD  (NPAIR + 128)

// ---------------- device scratch ---------------------------------------------
__device__ int   g_count[NEXP];
__device__ int   g_offset[NEXP];
__device__ int   g_pairs[NEXP][NTOK];      // value = token*2 + slot
__device__ int   g_ticket;                 // gate completion ticket (self-resets)
__device__ float g_gatew[NTOK][2];
__device__ __align__(128) float g_xs[MPAD][DDIM];   // gathered x, tf32-rounded
__device__ __align__(128) float g_h1[MPAD][FDIM];   // gemm1 out, tf32-rounded
__device__ __align__(128) float g_out2[NPAIR][DDIM];  // split 0 (+bias)
__device__ __align__(128) float g_out2b[NPAIR][DDIM]; // split 1

// ---------------- helpers -------------------------------------------------------
__device__ __forceinline__ uint32_t to_tf32(float f) {
    uint32_t r;
    asm("cvt.rna.tf32.f32 %0, %1;" : "=r"(r) : "f"(f));
    return r;
}
__device__ __forceinline__ uint32_t smem_u32(const void* p) {
    uint32_t a;
    asm("{ .reg .u64 t; cvta.to.shared.u64 t, %1; cvt.u32.u64 %0, t; }" : "=r"(a) : "l"(p));
    return a;
}

#define MMA_TF32(d, a, b0, b1) \
    asm volatile("mma.sync.aligned.m16n8k8.row.col.f32.tf32.tf32.f32 " \
        "{%0,%1,%2,%3},{%4,%5,%6,%7},{%8,%9},{%0,%1,%2,%3};" \
        : "+f"((d)[0]), "+f"((d)[1]), "+f"((d)[2]), "+f"((d)[3]) \
        : "r"((a)[0]), "r"((a)[1]), "r"((a)[2]), "r"((a)[3]), "r"(b0), "r"(b1))

#define LDSM4(r, addr) \
    asm volatile("ldmatrix.sync.aligned.m8n8.x4.shared.b16 {%0,%1,%2,%3}, [%4];" \
        : "=r"((r)[0]), "=r"((r)[1]), "=r"((r)[2]), "=r"((r)[3]) : "r"(addr))

#define CP16(d, s) \
    asm volatile("cp.async.cg.shared.global [%0], [%1], 16;" :: "r"(d), "l"(s) : "memory")
#define CP_COMMIT() asm volatile("cp.async.commit_group;" ::: "memory")
#define CP_WAIT1()  asm volatile("cp.async.wait_group 1;" ::: "memory")
#define CP_WAIT0()  asm volatile("cp.async.wait_group 0;" ::: "memory")

// ---------------- kernel: zero expert counts ----------------------------------
__global__ void zero_kernel() {
    if (threadIdx.x < NEXP) g_count[threadIdx.x] = 0;
    if (threadIdx.x == NEXP) g_ticket = 0;
}

// ---------------- kernel: gating — smem-staged weights, prefix folded in -------
// 8 warps = 8 tokens/block; gate_w staged in two 7-expert passes (28KB smem).
// Per-lane accumulation order and shuffle tree identical to proven version.
__global__ void gate_kernel(const float* __restrict__ x,
                            const float* __restrict__ gw) {
    __shared__ float sw[7][DDIM];
    int tid = threadIdx.x;
    int lane = tid & 31, wid = tid >> 5;
    int n = blockIdx.x * 8 + wid;
    const float4* xr = (const float4*)(x + (size_t)n * DDIM);
    float4 xv[8];
    #pragma unroll
    for (int i = 0; i < 8; i++) xv[i] = xr[i * 32 + lane];

    float l0 = -3.0e38f, l1 = -3.0e38f;
    int i0 = 0, i1 = -1;
    #pragma unroll
    for (int pass = 0; pass < 2; pass++) {
        // stage 7 expert rows: 7*1024/4 = 1792 float4, 256 threads x 7
        const float4* src = (const float4*)(gw + (size_t)pass * 7 * DDIM);
        float4* dst = (float4*)&sw[0][0];
        #pragma unroll
        for (int it = 0; it < 7; it++) dst[it * 256 + tid] = src[it * 256 + tid];
        __syncthreads();
        for (int ee = 0; ee < 7; ee++) {
            int e = pass * 7 + ee;
            const float4* we = (const float4*)&sw[ee][0];
            float s = 0.f;
            #pragma unroll
            for (int i = 0; i < 8; i++) {
                float4 b = we[i * 32 + lane];
                s += xv[i].x * b.x + xv[i].y * b.y + xv[i].z * b.z + xv[i].w * b.w;
            }
            #pragma unroll
            for (int o = 16; o; o >>= 1) s += __shfl_xor_sync(0xFFFFFFFFu, s, o);
            if (s > l0)      { l1 = l0; i1 = i0; l0 = s; i0 = e; }
            else if (s > l1) { l1 = s;  i1 = e; }
        }
        __syncthreads();
    }
    if (lane == 0) {
        float p1 = expf(l1 - l0);
        float inv = 1.0f / (1.0f + p1);
        g_gatew[n][0] = inv;
        g_gatew[n][1] = p1 * inv;
        int s0 = atomicAdd(&g_count[i0], 1);
        g_pairs[i0][s0] = n * 2 + 0;
        int s1 = atomicAdd(&g_count[i1], 1);
        g_pairs[i1][s1] = n * 2 + 1;
    }
    // last finishing block computes exclusive prefix (replaces prefix_kernel)
    __syncthreads();
    if (tid == 0) {
        int t = atomicAdd(&g_ticket, 1);
        if (t == gridDim.x - 1) {
            int s = 0;
            for (int e = 0; e < NEXP; e++) { g_offset[e] = s; s += g_count[e]; }
            g_ticket = 0;   // reset for next graph replay
        }
    }
}

// ---------------- gather (sort fused): expert-sorted x rows, tf32-rounded -------
__global__ void gather_x(const float* __restrict__ x) {
    int row = blockIdx.x;                  // 0..MPAD-1
    int tid = threadIdx.x;                 // 256 threads, 1 float4 each
    float4 v = make_float4(0.f, 0.f, 0.f, 0.f);
    if (row < NPAIR) {
        // find expert bucket: off[e] <= row < off[e]+cnt[e]
        int e = NEXP - 1;
        #pragma unroll
        for (int k = NEXP - 1; k > 0; k--)
            if (row < g_offset[k]) e = k - 1;
        int pair = g_pairs[e][row - g_offset[e]];
        int tok = pair >> 1;
        v = ((const float4*)(x + (size_t)tok * DDIM))[tid];
    }
    uint4 r = make_uint4(to_tf32(v.x), to_tf32(v.y), to_tf32(v.z), to_tf32(v.w));
    ((uint4*)(g_xs[row]))[tid] = r;
}

// =================================================================================
// TF32 GEMM — all operands via cp.async (A pre-rounded in gmem, B raw-truncated).
//   SA[2]: [128 m][20 u32] (80B stride), frags via ldmatrix.x4 (proven).
//   SB[3]: [16 k][136 u32] (544B stride), frags via scalar LDS (proven).
//   Per-phase group order: [A(c+1)], [B(c+2)]; wait_group 1 at phase top ->
//   A(c) + B(c) complete, B(c+1) may remain in flight. Tail phases commit
//   empty groups to keep the accounting identical.
//   8 warps = 2(m) x 4(n); warp tile 64x32; m16n8k8 tf32, fp32 accum.
// =================================================================================
#define SA_BUFB 10240u   // 128*20*4
#define SB_BUFB 8704u    // 16*136*4

// ---------------- GEMM1: h1 = gelu(g_xs @ w1 + b1), tf32-rounded store ----------
__global__ void __launch_bounds__(256, 2)
gemm1_mma(const float* __restrict__ w1,
          const float* __restrict__ b1) {
    int e = blockIdx.z, mt = blockIdx.y;
    int cnt = g_count[e];
    if (mt * 128 >= cnt) return;
    int nt = blockIdx.x;
    int off = g_offset[e];
    int mrow0 = off + mt * 128;

    __shared__ __align__(16) uint32_t SA[2][128][20];
    __shared__ __align__(16) uint32_t SB[3][16][136];

    int tid = threadIdx.x, lane = tid & 31, wid = tid >> 5;
    int wm = wid & 1, wn = wid >> 1;
    int g = lane >> 2, tig = lane & 3;

    int lm = tid & 127, kh = tid >> 7;
    const float* arow = &g_xs[mrow0 + lm][kh * 8];
    uint32_t dA0 = smem_u32(&SA[0][lm][kh * 8]);
    int bk = tid >> 5, bn = (tid & 31) * 4;
    const float* bsrc = w1 + (size_t)e * DDIM * FDIM + (size_t)bk * FDIM + nt * 128 + bn;
    uint32_t dB0 = smem_u32(&SB[0][bk][bn]);

    auto cpA = [&](int c, int slot) {
        const float* s = arow + (size_t)c * 16;
        uint32_t d = dA0 + slot * SA_BUFB;
        CP16(d, s);
        CP16(d + 16, s + 4);
        CP_COMMIT();
    };
    auto cpB = [&](int c, uint32_t d) {
        const float* s = bsrc + (size_t)(c * 16) * FDIM;
        CP16(d, s);
        CP16(d + 8 * 544, s + (size_t)8 * FDIM);
        CP_COMMIT();
    };

    uint32_t aA0 = smem_u32(&SA[0][0][0]) + (wm * 64 + (lane & 15)) * 80 + (lane >> 4) * 16;
    int bn0 = wn * 32 + (lane >> 2);
    int bk0 = lane & 3;

    float acc[4][4][4] = {};

    auto compute = [&](uint32_t aAb, const uint32_t (*sB)[136]) {
        uint32_t bf[4][2][2];
        #pragma unroll
        for (int t = 0; t < 4; t++)
            #pragma unroll
            for (int ks = 0; ks < 2; ks++) {
                bf[t][ks][0] = sB[ks * 8 + bk0][bn0 + t * 8];
                bf[t][ks][1] = sB[ks * 8 + bk0 + 4][bn0 + t * 8];
            }
        #pragma unroll
        for (int ks = 0; ks < 2; ks++)
            #pragma unroll
            for (int i = 0; i < 4; i++) {
                uint32_t a[4];
                LDSM4(a, aAb + ks * 32 + i * 1280);
                MMA_TF32(acc[i][0], a, bf[0][ks][0], bf[0][ks][1]);
                MMA_TF32(acc[i][1], a, bf[1][ks][0], bf[1][ks][1]);
                MMA_TF32(acc[i][2], a, bf[2][ks][0], bf[2][ks][1]);
                MMA_TF32(acc[i][3], a, bf[3][ks][0], bf[3][ks][1]);
            }
    };

    const int NCH = DDIM / 16;   // 64
    cpA(0, 0);
    cpB(0, dB0);
    cpB(1, dB0 + SB_BUFB);

    uint32_t wrB = dB0 + 2 * SB_BUFB;
    const uint32_t wrBhi = dB0 + 2 * SB_BUFB;
    const uint32_t (*rdB)[136] = SB[0];
    uint32_t aOff = 0;

    for (int c = 0; c < NCH; c++) {
        CP_WAIT1();                 // A(c), B(c) complete; B(c+1) may be in flight
        __syncthreads();
        if (c + 1 < NCH) cpA(c + 1, (c + 1) & 1); else CP_COMMIT();
        if (c + 2 < NCH) {
            cpB(c + 2, wrB);
            wrB += SB_BUFB;
            if (wrB > wrBhi) wrB -= 3 * SB_BUFB;
        } else CP_COMMIT();
        compute(aA0 + aOff, rdB);
        aOff ^= SA_BUFB;
        rdB = (rdB == SB[2]) ? SB[0] : rdB + 16;
    }
    CP_WAIT0();

    // epilogue: bias + exact gelu, tf32-rounded store to g_h1
    int lim = cnt - mt * 128; if (lim > 128) lim = 128;
    const float* b1e = b1 + (size_t)e * FDIM + nt * 128;
    #pragma unroll
    for (int i = 0; i < 4; i++) {
        #pragma unroll
        for (int t = 0; t < 4; t++) {
            int col = wn * 32 + t * 8 + tig * 2;
            float bA = b1e[col], bB = b1e[col + 1];
            #pragma unroll
            for (int half = 0; half < 2; half++) {
                int r = wm * 64 + i * 16 + g + half * 8;
                if (r < lim) {
                    float v0 = acc[i][t][half * 2 + 0] + bA;
                    float v1 = acc[i][t][half * 2 + 1] + bB;
                    v0 = 0.5f * v0 * (1.0f + erff(v0 * 0.70710678118654752440f));
                    v1 = 0.5f * v1 * (1.0f + erff(v1 * 0.70710678118654752440f));
                    *(float2*)&g_h1[mrow0 + r][nt * 128 + col] =
                        make_float2(__uint_as_float(to_tf32(v0)),
                                    __uint_as_float(to_tf32(v1)));
                }
            }
        }
    }
}

// ---------------- GEMM2 (split-K x2): out2[s] = h1[:, sK:] @ w2[sK:, :] ----------
__global__ void __launch_bounds__(256, 2)
gemm2_mma(const float* __restrict__ w2,
          const float* __restrict__ b2) {
    int ez = blockIdx.z;
    int e = ez >> 1, sp = ez & 1;
    int mt = blockIdx.y;
    int cnt = g_count[e];
    if (mt * 128 >= cnt) return;
    int nt = blockIdx.x;
    int off = g_offset[e];
    int mrow0 = off + mt * 128;

    __shared__ __align__(16) uint32_t SA[2][128][20];
    __shared__ __align__(16) uint32_t SB[3][16][136];
    __shared__ int pid[128];

    int tid = threadIdx.x, lane = tid & 31, wid = tid >> 5;
    int wm = wid & 1, wn = wid >> 1;
    int g = lane >> 2, tig = lane & 3;

    if (tid < 128) {
        int m = mt * 128 + tid;
        pid[tid] = (m < cnt) ? g_pairs[e][m] : 0;
    }
    __syncthreads();

    int lm = tid & 127, kh = tid >> 7;
    const float* arow = &g_h1[mrow0 + lm][sp * 1024 + kh * 8];
    uint32_t dA0 = smem_u32(&SA[0][lm][kh * 8]);
    int bk = tid >> 5, bn = (tid & 31) * 4;
    const float* bsrc = w2 + (size_t)e * FDIM * DDIM
                      + (size_t)(sp * 1024 + bk) * DDIM + nt * 128 + bn;
    uint32_t dB0 = smem_u32(&SB[0][bk][bn]);

    auto cpA = [&](int c, int slot) {
        const float* s = arow + (size_t)c * 16;
        uint32_t d = dA0 + slot * SA_BUFB;
        CP16(d, s);
        CP16(d + 16, s + 4);
        CP_COMMIT();
    };
    auto cpB = [&](int c, uint32_t d) {
        const float* s = bsrc + (size_t)(c * 16) * DDIM;
        CP16(d, s);
        CP16(d + 8 * 544, s + (size_t)8 * DDIM);
        CP_COMMIT();
    };

    uint32_t aA0 = smem_u32(&SA[0][0][0]) + (wm * 64 + (lane & 15)) * 80 + (lane >> 4) * 16;
    int bn0 = wn * 32 + (lane >> 2);
    int bk0 = lane & 3;

    float acc[4][4][4] = {};

    auto compute = [&](uint32_t aAb, const uint32_t (*sB)[136]) {
        uint32_t bf[4][2][2];
        #pragma unroll
        for (int t = 0; t < 4; t++)
            #pragma unroll
            for (int ks = 0; ks < 2; ks++) {
                bf[t][ks][0] = sB[ks * 8 + bk0][bn0 + t * 8];
                bf[t][ks][1] = sB[ks * 8 + bk0 + 4][bn0 + t * 8];
            }
        #pragma unroll
        for (int ks = 0; ks < 2; ks++)
            #pragma unroll
            for (int i = 0; i < 4; i++) {
                uint32_t a[4];
                LDSM4(a, aAb + ks * 32 + i * 1280);
                MMA_TF32(acc[i][0], a, bf[0][ks][0], bf[0][ks][1]);
                MMA_TF32(acc[i][1], a, bf[1][ks][0], bf[1][ks][1]);
                MMA_TF32(acc[i][2], a, bf[2][ks][0], bf[2][ks][1]);
                MMA_TF32(acc[i][3], a, bf[3][ks][0], bf[3][ks][1]);
            }
    };

    const int NCH = 1024 / 16;   // 64 per split
    cpA(0, 0);
    cpB(0, dB0);
    cpB(1, dB0 + SB_BUFB);

    uint32_t wrB = dB0 + 2 * SB_BUFB;
    const uint32_t wrBhi = dB0 + 2 * SB_BUFB;
    const uint32_t (*rdB)[136] = SB[0];
    uint32_t aOff = 0;

    for (int c = 0; c < NCH; c++) {
        CP_WAIT1();
        __syncthreads();
        if (c + 1 < NCH) cpA(c + 1, (c + 1) & 1); else CP_COMMIT();
        if (c + 2 < NCH) {
            cpB(c + 2, wrB);
            wrB += SB_BUFB;
            if (wrB > wrBhi) wrB -= 3 * SB_BUFB;
        } else CP_COMMIT();
        compute(aA0 + aOff, rdB);
        aOff ^= SA_BUFB;
        rdB = (rdB == SB[2]) ? SB[0] : rdB + 16;
    }
    CP_WAIT0();

    // epilogue: split 0 adds bias -> g_out2; split 1 raw -> g_out2b
    int lim = cnt - mt * 128; if (lim > 128) lim = 128;
    const float* b2e = b2 + (size_t)e * DDIM + nt * 128;
    #pragma unroll
    for (int i = 0; i < 4; i++) {
        #pragma unroll
        for (int t = 0; t < 4; t++) {
            int col = wn * 32 + t * 8 + tig * 2;
            float bA = sp ? 0.f : b2e[col];
            float bB = sp ? 0.f : b2e[col + 1];
            #pragma unroll
            for (int half = 0; half < 2; half++) {
                int r = wm * 64 + i * 16 + g + half * 8;
                if (r < lim) {
                    int pr = pid[r];
                    float* dst = sp ? &g_out2b[pr][nt * 128 + col]
                                    : &g_out2[pr][nt * 128 + col];
                    *(float2*)dst = make_float2(acc[i][t][half * 2 + 0] + bA,
                                                acc[i][t][half * 2 + 1] + bB);
                }
            }
        }
    }
}

// ---------------- combine: out = clip(x + w0*(o0a+o0b) + w1*(o1a+o1b)) ----------
__global__ void combine_kernel(const float* __restrict__ x,
                               float* __restrict__ out) {
    int i = blockIdx.x * 256 + threadIdx.x;
    int n = i >> 10;
    int d = i & 1023;
    float o0 = g_out2[2 * n + 0][d] + g_out2b[2 * n + 0][d];
    float o1 = g_out2[2 * n + 1][d] + g_out2b[2 * n + 1][d];
    float v = x[i] + g_gatew[n][0] * o0 + g_gatew[n][1] * o1;
    out[i] = fminf(fmaxf(v, -100.0f), 100.0f);
}

// ---------------- launch --------------------------------------------------------
extern "C" void kernel_launch(void* const* d_in, const int* in_sizes, int n_in,
                              void* d_out, int out_size) {
    const float* h      = (const float*)d_in[0];   // (2,1024,1024)
    const float* gate_w = (const float*)d_in[1];   // (14,1024)
    const float* w1     = (const float*)d_in[2];   // (14,1024,2048)
    const float* b1     = (const float*)d_in[3];   // (14,2048)
    const float* w2     = (const float*)d_in[4];   // (14,2048,1024)
    const float* b2     = (const float*)d_in[5];   // (14,1024)
    float* out = (float*)d_out;

    zero_kernel<<<1, 32>>>();
    gate_kernel<<<NTOK / 8, 256>>>(h, gate_w);
    gather_x<<<MPAD, 256>>>(h);
    gemm1_mma<<<dim3(FDIM / 128, NTOK / 128, NEXP), 256>>>(w1, b1);
    gemm2_mma<<<dim3(DDIM / 128, NTOK / 128, NEXP * 2), 256>>>(w2, b2);
    combine_kernel<<<(NTOK * DDIM) / 256, 256>>>(h, out);
}